// round 1
// baseline (speedup 1.0000x reference)
#include <cuda_runtime.h>
#include <math.h>

// Problem constants
#define NTOK 4096
#define DIM  1024
#define NEXP 8
#define TOPK 2
#define IDIM 2048
#define CAP  1280          // int(4096*2*1.25/8)
#define NSLOT (NTOK*TOPK)  // 8192

// Scratch (static device allocations; no cudaMalloc allowed)
__device__ float g_hglu[(size_t)NEXP * CAP * IDIM];   // 83.9 MB: GLU activations
__device__ int   g_row2tok[NEXP * CAP];
__device__ float g_rowgate[NEXP * CAP];
__device__ int   g_count[NEXP];
__device__ int   g_slot_e[NSLOT];
__device__ float g_slot_g[NSLOT];

// ---------------------------------------------------------------------------
// Router: one warp per token. logits = x @ Wg^T, top-2, softmax over top-2.
// ---------------------------------------------------------------------------
__global__ void router_kernel(const float* __restrict__ x,
                              const float* __restrict__ Wg) {
    int warp = (blockIdx.x * blockDim.x + threadIdx.x) >> 5;
    int lane = threadIdx.x & 31;
    if (warp >= NTOK) return;
    const float* xr = x + (size_t)warp * DIM;
    float acc[NEXP];
#pragma unroll
    for (int e = 0; e < NEXP; e++) acc[e] = 0.f;
    for (int i = lane; i < DIM; i += 32) {
        float xv = __ldg(xr + i);
#pragma unroll
        for (int e = 0; e < NEXP; e++) acc[e] += xv * __ldg(Wg + e * DIM + i);
    }
#pragma unroll
    for (int e = 0; e < NEXP; e++) {
#pragma unroll
        for (int off = 16; off > 0; off >>= 1)
            acc[e] += __shfl_xor_sync(0xffffffffu, acc[e], off);
    }
    if (lane == 0) {
        // top-2 (strict > keeps lowest index on ties, matching jax top_k)
        int i0 = 0; float v0 = acc[0];
#pragma unroll
        for (int e = 1; e < NEXP; e++) if (acc[e] > v0) { v0 = acc[e]; i0 = e; }
        int i1 = -1; float v1 = -1e30f;
#pragma unroll
        for (int e = 0; e < NEXP; e++)
            if (e != i0 && acc[e] > v1) { v1 = acc[e]; i1 = e; }
        float e0 = expf(v0 - v0), e1 = expf(v1 - v0);
        float inv = 1.0f / (e0 + e1);
        g_slot_e[2 * warp + 0] = i0; g_slot_g[2 * warp + 0] = e0 * inv;
        g_slot_e[2 * warp + 1] = i1; g_slot_g[2 * warp + 1] = e1 * inv;
    }
}

// ---------------------------------------------------------------------------
// Capacity scan: single block. Slot order = token-major then k, exactly like
// the reference cumsum(onehot). pos = count of earlier slots with same expert,
// keep if pos < CAP. Builds row->token / row->gate maps.
// ---------------------------------------------------------------------------
__global__ void scan_kernel() {
    __shared__ int smc[256][NEXP];
    int tid = threadIdx.x;
    // deterministic default fill for unused rows (token 0, gate 0)
    for (int i = tid; i < NEXP * CAP; i += 256) {
        g_row2tok[i] = 0;
        g_rowgate[i] = 0.f;
    }
    const int PER = NSLOT / 256; // 32
    int s0 = tid * PER;
    int le[PER];
    int c[NEXP];
#pragma unroll
    for (int e = 0; e < NEXP; e++) c[e] = 0;
#pragma unroll
    for (int j = 0; j < PER; j++) {
        int e = g_slot_e[s0 + j];
        le[j] = e;
        c[e]++;
    }
#pragma unroll
    for (int e = 0; e < NEXP; e++) smc[tid][e] = c[e];
    __syncthreads();
    if (tid < NEXP) {
        int run = 0;
        for (int t = 0; t < 256; t++) {
            int v = smc[t][tid];
            smc[t][tid] = run;
            run += v;
        }
        g_count[tid] = run < CAP ? run : CAP;
    }
    __syncthreads();
    int off[NEXP];
#pragma unroll
    for (int e = 0; e < NEXP; e++) off[e] = smc[tid][e];
#pragma unroll
    for (int j = 0; j < PER; j++) {
        int e = le[j];
        int p = off[e]++;
        if (p < CAP) {
            int slot = s0 + j;
            g_row2tok[e * CAP + p] = slot >> 1;
            g_rowgate[e * CAP + p] = g_slot_g[slot];
        }
    }
}

// ---------------------------------------------------------------------------
// GEMM1 + gather + GLU: h_glu[e][r][j] = gelu(A@W1[:, j]) * (A@W1[:, j+I])
// A[r] = x[row2tok[e, r]]. Tile: BM=128, BN=64, BK=16, 256 thr, 8x4 microtile.
// ---------------------------------------------------------------------------
#define BM 128
#define BN 64
#define BK 16

__global__ __launch_bounds__(256) void gemm1_kernel(const float* __restrict__ x,
                                                    const float* __restrict__ W1) {
    __shared__ float As[BK][BM];
    __shared__ float B1s[BK][BN];
    __shared__ float B2s[BK][BN];
    __shared__ int stok[BM];

    int e  = blockIdx.z;
    int n0 = blockIdx.x * BN;     // GLU output column base (0..2047)
    int r0 = blockIdx.y * BM;     // expert row base
    int tid = threadIdx.x;

    if (tid < BM) stok[tid] = g_row2tok[e * CAP + r0 + tid];
    __syncthreads();

    const float* W1e = W1 + (size_t)e * DIM * (2 * IDIM);

    int arow = tid >> 1;            // 0..127
    int acol = (tid & 1) * 8;       // 0 or 8
    int bkk  = tid >> 4;            // 0..15
    int bj4  = (tid & 15) * 4;      // 0..60
    int tr   = tid >> 4;            // 0..15 (row group)
    int tc   = tid & 15;            // 0..15 (col group)

    float acc1[8][4], acc2[8][4];
#pragma unroll
    for (int i = 0; i < 8; i++)
#pragma unroll
        for (int j = 0; j < 4; j++) { acc1[i][j] = 0.f; acc2[i][j] = 0.f; }

    for (int k0 = 0; k0 < DIM; k0 += BK) {
        const float* xp = x + (size_t)stok[arow] * DIM + k0 + acol;
        float4 a0 = *(const float4*)xp;
        float4 a1 = *(const float4*)(xp + 4);
        As[acol + 0][arow] = a0.x; As[acol + 1][arow] = a0.y;
        As[acol + 2][arow] = a0.z; As[acol + 3][arow] = a0.w;
        As[acol + 4][arow] = a1.x; As[acol + 5][arow] = a1.y;
        As[acol + 6][arow] = a1.z; As[acol + 7][arow] = a1.w;

        const float* bp = W1e + (size_t)(k0 + bkk) * (2 * IDIM) + n0 + bj4;
        *(float4*)&B1s[bkk][bj4] = *(const float4*)bp;
        *(float4*)&B2s[bkk][bj4] = *(const float4*)(bp + IDIM);
        __syncthreads();

#pragma unroll
        for (int kk = 0; kk < BK; kk++) {
            float a[8], b1[4], b2[4];
            *(float4*)(a)     = *(const float4*)(&As[kk][tr * 8]);
            *(float4*)(a + 4) = *(const float4*)(&As[kk][tr * 8 + 4]);
            *(float4*)(b1)    = *(const float4*)(&B1s[kk][tc * 4]);
            *(float4*)(b2)    = *(const float4*)(&B2s[kk][tc * 4]);
#pragma unroll
            for (int i = 0; i < 8; i++)
#pragma unroll
                for (int j = 0; j < 4; j++) {
                    acc1[i][j] += a[i] * b1[j];
                    acc2[i][j] += a[i] * b2[j];
                }
        }
        __syncthreads();
    }

    // epilogue: exact gelu(inp) * gate
#pragma unroll
    for (int i = 0; i < 8; i++) {
        int r = r0 + tr * 8 + i;
        float4 v;
        float* vv = (float*)&v;
#pragma unroll
        for (int j = 0; j < 4; j++) {
            float in = acc1[i][j];
            float gl = 0.5f * in * (1.0f + erff(in * 0.70710678118654752f));
            vv[j] = gl * acc2[i][j];
        }
        *(float4*)(g_hglu + ((size_t)(e * CAP + r)) * IDIM + n0 + tc * 4) = v;
    }
}

// ---------------------------------------------------------------------------
// GEMM2 + gate-weighted scatter: out[token] += gate * (h_glu[e] @ W2[e])[r]
// ---------------------------------------------------------------------------
__global__ __launch_bounds__(256) void gemm2_kernel(const float* __restrict__ W2,
                                                    float* __restrict__ out) {
    __shared__ float As[BK][BM];
    __shared__ float Bs[BK][BN];

    int e  = blockIdx.z;
    int n0 = blockIdx.x * BN;     // output dim column base
    int r0 = blockIdx.y * BM;
    int cnt = g_count[e];
    if (r0 >= cnt) return;        // tile entirely beyond used rows
    int tid = threadIdx.x;

    const float* W2e = W2 + (size_t)e * IDIM * DIM;
    const float* Ae  = g_hglu + (size_t)e * CAP * IDIM;

    int arow = tid >> 1;
    int acol = (tid & 1) * 8;
    int bkk  = tid >> 4;
    int bj4  = (tid & 15) * 4;
    int tr   = tid >> 4;
    int tc   = tid & 15;

    float acc[8][4];
#pragma unroll
    for (int i = 0; i < 8; i++)
#pragma unroll
        for (int j = 0; j < 4; j++) acc[i][j] = 0.f;

    for (int k0 = 0; k0 < IDIM; k0 += BK) {
        const float* ap = Ae + (size_t)(r0 + arow) * IDIM + k0 + acol;
        float4 a0 = *(const float4*)ap;
        float4 a1 = *(const float4*)(ap + 4);
        As[acol + 0][arow] = a0.x; As[acol + 1][arow] = a0.y;
        As[acol + 2][arow] = a0.z; As[acol + 3][arow] = a0.w;
        As[acol + 4][arow] = a1.x; As[acol + 5][arow] = a1.y;
        As[acol + 6][arow] = a1.z; As[acol + 7][arow] = a1.w;

        const float* bp = W2e + (size_t)(k0 + bkk) * DIM + n0 + bj4;
        *(float4*)&Bs[bkk][bj4] = *(const float4*)bp;
        __syncthreads();

#pragma unroll
        for (int kk = 0; kk < BK; kk++) {
            float a[8], b[4];
            *(float4*)(a)     = *(const float4*)(&As[kk][tr * 8]);
            *(float4*)(a + 4) = *(const float4*)(&As[kk][tr * 8 + 4]);
            *(float4*)(b)     = *(const float4*)(&Bs[kk][tc * 4]);
#pragma unroll
            for (int i = 0; i < 8; i++)
#pragma unroll
                for (int j = 0; j < 4; j++) acc[i][j] += a[i] * b[j];
        }
        __syncthreads();
    }

#pragma unroll
    for (int i = 0; i < 8; i++) {
        int r = r0 + tr * 8 + i;
        if (r < cnt) {
            int tok   = g_row2tok[e * CAP + r];
            float gte = g_rowgate[e * CAP + r];
            float* op = out + (size_t)tok * DIM + n0 + tc * 4;
#pragma unroll
            for (int j = 0; j < 4; j++) atomicAdd(op + j, gte * acc[i][j]);
        }
    }
}

// ---------------------------------------------------------------------------
extern "C" void kernel_launch(void* const* d_in, const int* in_sizes, int n_in,
                              void* d_out, int out_size) {
    const float* x  = (const float*)d_in[0];   // [2,2048,1024]
    const float* Wg = (const float*)d_in[1];   // [8,1024]
    const float* W1 = (const float*)d_in[2];   // [8,1024,4096]
    const float* W2 = (const float*)d_in[3];   // [8,2048,1024]
    float* out = (float*)d_out;                // [2,2048,1024]

    cudaMemsetAsync(out, 0, (size_t)NTOK * DIM * sizeof(float));

    router_kernel<<<NTOK / 8, 256>>>(x, Wg);
    scan_kernel<<<1, 256>>>();

    dim3 g1(IDIM / BN, CAP / BM, NEXP);   // (32, 10, 8)
    gemm1_kernel<<<g1, 256>>>(x, W1);

    dim3 g2(DIM / BN, CAP / BM, NEXP);    // (16, 10, 8)
    gemm2_kernel<<<g2, 256>>>(W2, out);
}

// round 2
// speedup vs baseline: 2.0202x; 2.0202x over previous
#include <cuda_runtime.h>
#include <math.h>

// Problem constants
#define NTOK 4096
#define DIM  1024
#define NEXP 8
#define TOPK 2
#define IDIM 2048
#define CAP  1280          // int(4096*2*1.25/8)
#define NSLOT (NTOK*TOPK)  // 8192

// Scratch (static device allocations; no cudaMalloc allowed)
__device__ float g_hglu[(size_t)NEXP * CAP * IDIM];   // 83.9 MB: GLU activations
__device__ int   g_row2tok[NEXP * CAP];
__device__ float g_rowgate[NEXP * CAP];
__device__ int   g_count[NEXP];
__device__ int   g_slot_e[NSLOT];
__device__ float g_slot_g[NSLOT];

__device__ __forceinline__ unsigned f2tf32(float f) {
    unsigned r;
    asm("cvt.rna.tf32.f32 %0, %1;" : "=r"(r) : "f"(f));
    return r;
}

__device__ __forceinline__ void mma_tf32(float* c, const unsigned* a, unsigned b0, unsigned b1) {
    asm volatile(
        "mma.sync.aligned.m16n8k8.row.col.f32.tf32.tf32.f32 "
        "{%0,%1,%2,%3}, {%4,%5,%6,%7}, {%8,%9}, {%0,%1,%2,%3};\n"
        : "+f"(c[0]), "+f"(c[1]), "+f"(c[2]), "+f"(c[3])
        : "r"(a[0]), "r"(a[1]), "r"(a[2]), "r"(a[3]), "r"(b0), "r"(b1));
}

// ---------------------------------------------------------------------------
// Router: one warp per token. logits = x @ Wg^T, top-2, softmax over top-2.
// ---------------------------------------------------------------------------
__global__ void router_kernel(const float* __restrict__ x,
                              const float* __restrict__ Wg) {
    int warp = (blockIdx.x * blockDim.x + threadIdx.x) >> 5;
    int lane = threadIdx.x & 31;
    if (warp >= NTOK) return;
    const float* xr = x + (size_t)warp * DIM;
    float acc[NEXP];
#pragma unroll
    for (int e = 0; e < NEXP; e++) acc[e] = 0.f;
    for (int i = lane; i < DIM; i += 32) {
        float xv = __ldg(xr + i);
#pragma unroll
        for (int e = 0; e < NEXP; e++) acc[e] += xv * __ldg(Wg + e * DIM + i);
    }
#pragma unroll
    for (int e = 0; e < NEXP; e++) {
#pragma unroll
        for (int off = 16; off > 0; off >>= 1)
            acc[e] += __shfl_xor_sync(0xffffffffu, acc[e], off);
    }
    if (lane == 0) {
        int i0 = 0; float v0 = acc[0];
#pragma unroll
        for (int e = 1; e < NEXP; e++) if (acc[e] > v0) { v0 = acc[e]; i0 = e; }
        int i1 = -1; float v1 = -1e30f;
#pragma unroll
        for (int e = 0; e < NEXP; e++)
            if (e != i0 && acc[e] > v1) { v1 = acc[e]; i1 = e; }
        float e0 = expf(v0 - v0), e1 = expf(v1 - v0);
        float inv = 1.0f / (e0 + e1);
        g_slot_e[2 * warp + 0] = i0; g_slot_g[2 * warp + 0] = e0 * inv;
        g_slot_e[2 * warp + 1] = i1; g_slot_g[2 * warp + 1] = e1 * inv;
    }
}

// ---------------------------------------------------------------------------
// Capacity scan: single block, slot order = token-major then k (matches the
// reference cumsum(onehot)).
// ---------------------------------------------------------------------------
__global__ void scan_kernel() {
    __shared__ int smc[256][NEXP];
    int tid = threadIdx.x;
    for (int i = tid; i < NEXP * CAP; i += 256) {
        g_row2tok[i] = 0;
        g_rowgate[i] = 0.f;
    }
    const int PER = NSLOT / 256; // 32
    int s0 = tid * PER;
    int le[PER];
    int c[NEXP];
#pragma unroll
    for (int e = 0; e < NEXP; e++) c[e] = 0;
#pragma unroll
    for (int j = 0; j < PER; j++) {
        int e = g_slot_e[s0 + j];
        le[j] = e;
        c[e]++;
    }
#pragma unroll
    for (int e = 0; e < NEXP; e++) smc[tid][e] = c[e];
    __syncthreads();
    if (tid < NEXP) {
        int run = 0;
        for (int t = 0; t < 256; t++) {
            int v = smc[t][tid];
            smc[t][tid] = run;
            run += v;
        }
        g_count[tid] = run < CAP ? run : CAP;
    }
    __syncthreads();
    int off[NEXP];
#pragma unroll
    for (int e = 0; e < NEXP; e++) off[e] = smc[tid][e];
#pragma unroll
    for (int j = 0; j < PER; j++) {
        int e = le[j];
        int p = off[e]++;
        if (p < CAP) {
            int slot = s0 + j;
            g_row2tok[e * CAP + p] = slot >> 1;
            g_rowgate[e * CAP + p] = g_slot_g[slot];
        }
    }
}

// ---------------------------------------------------------------------------
// GEMM1 (tf32 tensor cores) + gather + GLU.
// Block tile: 128 rows x 64 GLU cols (computes both inp and gate halves).
// 8 warps, warp tile 32x32 per B-matrix, m16n8k8 mma.
// ---------------------------------------------------------------------------
#define BK 16

__global__ __launch_bounds__(256) void gemm1_kernel(const float* __restrict__ x,
                                                    const float* __restrict__ W1) {
    __shared__ unsigned As[BK][132];
    __shared__ unsigned B1s[BK][68];
    __shared__ unsigned B2s[BK][68];
    __shared__ int stok[128];

    int e  = blockIdx.z;
    int cnt = g_count[e];
    int r0 = blockIdx.y * 128;
    if (r0 >= cnt) return;        // capacity skip
    int n0 = blockIdx.x * 64;     // GLU col base (0..2047)
    int tid = threadIdx.x;
    int lane = tid & 31;
    int warp = tid >> 5;
    int gid = lane >> 2;          // 0..7
    int tid4 = lane & 3;          // 0..3
    int warp_m = warp >> 1;       // 0..3 -> 32 rows each
    int warp_n = warp & 1;        // 0..1 -> 32 cols each

    if (tid < 128) stok[tid] = g_row2tok[e * CAP + r0 + tid];
    __syncthreads();

    const float* W1e = W1 + (size_t)e * DIM * (2 * IDIM);

    int arow = tid >> 1;
    int acol = (tid & 1) * 8;
    int bkk  = tid >> 4;
    int bj4  = (tid & 15) * 4;

    float c1[2][4][4], c2[2][4][4];
#pragma unroll
    for (int mt = 0; mt < 2; mt++)
#pragma unroll
        for (int nt = 0; nt < 4; nt++)
#pragma unroll
            for (int j = 0; j < 4; j++) { c1[mt][nt][j] = 0.f; c2[mt][nt][j] = 0.f; }

    for (int k0 = 0; k0 < DIM; k0 += BK) {
        const float* xp = x + (size_t)stok[arow] * DIM + k0 + acol;
        float4 a0 = *(const float4*)xp;
        float4 a1 = *(const float4*)(xp + 4);
        As[acol + 0][arow] = f2tf32(a0.x); As[acol + 1][arow] = f2tf32(a0.y);
        As[acol + 2][arow] = f2tf32(a0.z); As[acol + 3][arow] = f2tf32(a0.w);
        As[acol + 4][arow] = f2tf32(a1.x); As[acol + 5][arow] = f2tf32(a1.y);
        As[acol + 6][arow] = f2tf32(a1.z); As[acol + 7][arow] = f2tf32(a1.w);

        const float* bp = W1e + (size_t)(k0 + bkk) * (2 * IDIM) + n0 + bj4;
        float4 b1v = *(const float4*)bp;
        float4 b2v = *(const float4*)(bp + IDIM);
        B1s[bkk][bj4 + 0] = f2tf32(b1v.x); B1s[bkk][bj4 + 1] = f2tf32(b1v.y);
        B1s[bkk][bj4 + 2] = f2tf32(b1v.z); B1s[bkk][bj4 + 3] = f2tf32(b1v.w);
        B2s[bkk][bj4 + 0] = f2tf32(b2v.x); B2s[bkk][bj4 + 1] = f2tf32(b2v.y);
        B2s[bkk][bj4 + 2] = f2tf32(b2v.z); B2s[bkk][bj4 + 3] = f2tf32(b2v.w);
        __syncthreads();

#pragma unroll
        for (int kk = 0; kk < BK; kk += 8) {
            unsigned af[2][4];
#pragma unroll
            for (int mt = 0; mt < 2; mt++) {
                int m = warp_m * 32 + mt * 16 + gid;
                af[mt][0] = As[kk + tid4][m];
                af[mt][1] = As[kk + tid4][m + 8];
                af[mt][2] = As[kk + tid4 + 4][m];
                af[mt][3] = As[kk + tid4 + 4][m + 8];
            }
#pragma unroll
            for (int nt = 0; nt < 4; nt++) {
                int n = warp_n * 32 + nt * 8 + gid;
                unsigned b10 = B1s[kk + tid4][n];
                unsigned b11 = B1s[kk + tid4 + 4][n];
                unsigned b20 = B2s[kk + tid4][n];
                unsigned b21 = B2s[kk + tid4 + 4][n];
#pragma unroll
                for (int mt = 0; mt < 2; mt++) {
                    mma_tf32(c1[mt][nt], af[mt], b10, b11);
                    mma_tf32(c2[mt][nt], af[mt], b20, b21);
                }
            }
        }
        __syncthreads();
    }

    // epilogue: exact gelu(inp) * gate
#pragma unroll
    for (int mt = 0; mt < 2; mt++) {
#pragma unroll
        for (int half = 0; half < 2; half++) {
            int r = r0 + warp_m * 32 + mt * 16 + gid + half * 8;
#pragma unroll
            for (int nt = 0; nt < 4; nt++) {
                float i0 = c1[mt][nt][2 * half + 0];
                float i1 = c1[mt][nt][2 * half + 1];
                float g0 = 0.5f * i0 * (1.0f + erff(i0 * 0.70710678118654752f));
                float g1 = 0.5f * i1 * (1.0f + erff(i1 * 0.70710678118654752f));
                float2 v;
                v.x = g0 * c2[mt][nt][2 * half + 0];
                v.y = g1 * c2[mt][nt][2 * half + 1];
                int col = n0 + warp_n * 32 + nt * 8 + 2 * tid4;
                *(float2*)(g_hglu + ((size_t)(e * CAP + r)) * IDIM + col) = v;
            }
        }
    }
}

// ---------------------------------------------------------------------------
// GEMM2 (tf32 tensor cores) + gate-weighted scatter.
// Block tile: 128 rows x 128 out cols. 8 warps, warp tile 32x64.
// ---------------------------------------------------------------------------
__global__ __launch_bounds__(256) void gemm2_kernel(const float* __restrict__ W2,
                                                    float* __restrict__ out) {
    __shared__ unsigned As[BK][132];
    __shared__ unsigned Bs[BK][132];

    int e  = blockIdx.z;
    int cnt = g_count[e];
    int r0 = blockIdx.y * 128;
    if (r0 >= cnt) return;
    int n0 = blockIdx.x * 128;
    int tid = threadIdx.x;
    int lane = tid & 31;
    int warp = tid >> 5;
    int gid = lane >> 2;
    int tid4 = lane & 3;
    int warp_m = warp >> 1;       // 0..3 -> 32 rows
    int warp_n = warp & 1;        // 0..1 -> 64 cols

    const float* W2e = W2 + (size_t)e * IDIM * DIM;
    const float* Ae  = g_hglu + (size_t)e * CAP * IDIM;

    int arow = tid >> 1;
    int acol = (tid & 1) * 8;
    int bkk  = tid >> 4;
    int bj8  = (tid & 15) * 8;

    float c[2][8][4];
#pragma unroll
    for (int mt = 0; mt < 2; mt++)
#pragma unroll
        for (int nt = 0; nt < 8; nt++)
#pragma unroll
            for (int j = 0; j < 4; j++) c[mt][nt][j] = 0.f;

    for (int k0 = 0; k0 < IDIM; k0 += BK) {
        const float* ap = Ae + (size_t)(r0 + arow) * IDIM + k0 + acol;
        float4 a0 = *(const float4*)ap;
        float4 a1 = *(const float4*)(ap + 4);
        As[acol + 0][arow] = f2tf32(a0.x); As[acol + 1][arow] = f2tf32(a0.y);
        As[acol + 2][arow] = f2tf32(a0.z); As[acol + 3][arow] = f2tf32(a0.w);
        As[acol + 4][arow] = f2tf32(a1.x); As[acol + 5][arow] = f2tf32(a1.y);
        As[acol + 6][arow] = f2tf32(a1.z); As[acol + 7][arow] = f2tf32(a1.w);

        const float* bp = W2e + (size_t)(k0 + bkk) * DIM + n0 + bj8;
        float4 b0 = *(const float4*)bp;
        float4 b1 = *(const float4*)(bp + 4);
        Bs[bkk][bj8 + 0] = f2tf32(b0.x); Bs[bkk][bj8 + 1] = f2tf32(b0.y);
        Bs[bkk][bj8 + 2] = f2tf32(b0.z); Bs[bkk][bj8 + 3] = f2tf32(b0.w);
        Bs[bkk][bj8 + 4] = f2tf32(b1.x); Bs[bkk][bj8 + 5] = f2tf32(b1.y);
        Bs[bkk][bj8 + 6] = f2tf32(b1.z); Bs[bkk][bj8 + 7] = f2tf32(b1.w);
        __syncthreads();

#pragma unroll
        for (int kk = 0; kk < BK; kk += 8) {
            unsigned af[2][4];
#pragma unroll
            for (int mt = 0; mt < 2; mt++) {
                int m = warp_m * 32 + mt * 16 + gid;
                af[mt][0] = As[kk + tid4][m];
                af[mt][1] = As[kk + tid4][m + 8];
                af[mt][2] = As[kk + tid4 + 4][m];
                af[mt][3] = As[kk + tid4 + 4][m + 8];
            }
#pragma unroll
            for (int nt = 0; nt < 8; nt++) {
                int n = warp_n * 64 + nt * 8 + gid;
                unsigned b0 = Bs[kk + tid4][n];
                unsigned b1 = Bs[kk + tid4 + 4][n];
#pragma unroll
                for (int mt = 0; mt < 2; mt++)
                    mma_tf32(c[mt][nt], af[mt], b0, b1);
            }
        }
        __syncthreads();
    }

    // gate-weighted scatter with vector reductions
#pragma unroll
    for (int mt = 0; mt < 2; mt++) {
#pragma unroll
        for (int half = 0; half < 2; half++) {
            int r = r0 + warp_m * 32 + mt * 16 + gid + half * 8;
            if (r < cnt) {
                int tok   = g_row2tok[e * CAP + r];
                float gte = g_rowgate[e * CAP + r];
                float* op = out + (size_t)tok * DIM + n0 + warp_n * 64 + 2 * tid4;
#pragma unroll
                for (int nt = 0; nt < 8; nt++) {
                    float v0 = gte * c[mt][nt][2 * half + 0];
                    float v1 = gte * c[mt][nt][2 * half + 1];
                    asm volatile("red.global.add.v2.f32 [%0], {%1, %2};"
                                 :: "l"(op + nt * 8), "f"(v0), "f"(v1) : "memory");
                }
            }
        }
    }
}

// ---------------------------------------------------------------------------
extern "C" void kernel_launch(void* const* d_in, const int* in_sizes, int n_in,
                              void* d_out, int out_size) {
    const float* x  = (const float*)d_in[0];   // [2,2048,1024]
    const float* Wg = (const float*)d_in[1];   // [8,1024]
    const float* W1 = (const float*)d_in[2];   // [8,1024,4096]
    const float* W2 = (const float*)d_in[3];   // [8,2048,1024]
    float* out = (float*)d_out;                // [2,2048,1024]

    cudaMemsetAsync(out, 0, (size_t)NTOK * DIM * sizeof(float));

    router_kernel<<<NTOK / 8, 256>>>(x, Wg);
    scan_kernel<<<1, 256>>>();

    dim3 g1(IDIM / 64, CAP / 128, NEXP);   // (32, 10, 8)
    gemm1_kernel<<<g1, 256>>>(x, W1);

    dim3 g2(DIM / 128, CAP / 128, NEXP);   // (8, 10, 8)
    gemm2_kernel<<<g2, 256>>>(W2, out);
}

// round 3
// speedup vs baseline: 2.6658x; 1.3195x over previous
#include <cuda_runtime.h>
#include <math.h>

// Problem constants
#define NTOK 4096
#define DIM  1024
#define NEXP 8
#define TOPK 2
#define IDIM 2048
#define CAP  1280
#define NSLOT (NTOK*TOPK)
#define BK 16

// Scratch
__device__ float g_hglu[(size_t)NEXP * CAP * IDIM];   // 83.9 MB
__device__ int   g_row2tok[NEXP * CAP];
__device__ float g_rowgate[NEXP * CAP];
__device__ int   g_count[NEXP];
__device__ int   g_slot_e[NSLOT];
__device__ float g_slot_g[NSLOT];

__device__ __forceinline__ unsigned f2tf32(float f) {
    unsigned r;
    asm("cvt.rna.tf32.f32 %0, %1;" : "=r"(r) : "f"(f));
    return r;
}

__device__ __forceinline__ void mma_tf32(float* c, const unsigned* a, unsigned b0, unsigned b1) {
    asm volatile(
        "mma.sync.aligned.m16n8k8.row.col.f32.tf32.tf32.f32 "
        "{%0,%1,%2,%3}, {%4,%5,%6,%7}, {%8,%9}, {%0,%1,%2,%3};\n"
        : "+f"(c[0]), "+f"(c[1]), "+f"(c[2]), "+f"(c[3])
        : "r"(a[0]), "r"(a[1]), "r"(a[2]), "r"(a[3]), "r"(b0), "r"(b1));
}

// ---------------------------------------------------------------------------
// Router
// ---------------------------------------------------------------------------
__global__ void router_kernel(const float* __restrict__ x,
                              const float* __restrict__ Wg) {
    int warp = (blockIdx.x * blockDim.x + threadIdx.x) >> 5;
    int lane = threadIdx.x & 31;
    if (warp >= NTOK) return;
    const float* xr = x + (size_t)warp * DIM;
    float acc[NEXP];
#pragma unroll
    for (int e = 0; e < NEXP; e++) acc[e] = 0.f;
    for (int i = lane; i < DIM; i += 32) {
        float xv = __ldg(xr + i);
#pragma unroll
        for (int e = 0; e < NEXP; e++) acc[e] += xv * __ldg(Wg + e * DIM + i);
    }
#pragma unroll
    for (int e = 0; e < NEXP; e++) {
#pragma unroll
        for (int off = 16; off > 0; off >>= 1)
            acc[e] += __shfl_xor_sync(0xffffffffu, acc[e], off);
    }
    if (lane == 0) {
        int i0 = 0; float v0 = acc[0];
#pragma unroll
        for (int e = 1; e < NEXP; e++) if (acc[e] > v0) { v0 = acc[e]; i0 = e; }
        int i1 = -1; float v1 = -1e30f;
#pragma unroll
        for (int e = 0; e < NEXP; e++)
            if (e != i0 && acc[e] > v1) { v1 = acc[e]; i1 = e; }
        float e0 = expf(v0 - v0), e1 = expf(v1 - v0);
        float inv = 1.0f / (e0 + e1);
        g_slot_e[2 * warp + 0] = i0; g_slot_g[2 * warp + 0] = e0 * inv;
        g_slot_e[2 * warp + 1] = i1; g_slot_g[2 * warp + 1] = e1 * inv;
    }
}

// ---------------------------------------------------------------------------
// Capacity scan (single block; slot order token-major then k)
// ---------------------------------------------------------------------------
__global__ void scan_kernel() {
    __shared__ int smc[256][NEXP];
    int tid = threadIdx.x;
    for (int i = tid; i < NEXP * CAP; i += 256) {
        g_row2tok[i] = 0;
        g_rowgate[i] = 0.f;
    }
    const int PER = NSLOT / 256;
    int s0 = tid * PER;
    int le[PER];
    int c[NEXP];
#pragma unroll
    for (int e = 0; e < NEXP; e++) c[e] = 0;
#pragma unroll
    for (int j = 0; j < PER; j++) {
        int e = g_slot_e[s0 + j];
        le[j] = e;
        c[e]++;
    }
#pragma unroll
    for (int e = 0; e < NEXP; e++) smc[tid][e] = c[e];
    __syncthreads();
    if (tid < NEXP) {
        int run = 0;
        for (int t = 0; t < 256; t++) {
            int v = smc[t][tid];
            smc[t][tid] = run;
            run += v;
        }
        g_count[tid] = run < CAP ? run : CAP;
    }
    __syncthreads();
    int off[NEXP];
#pragma unroll
    for (int e = 0; e < NEXP; e++) off[e] = smc[tid][e];
#pragma unroll
    for (int j = 0; j < PER; j++) {
        int e = le[j];
        int p = off[e]++;
        if (p < CAP) {
            int slot = s0 + j;
            g_row2tok[e * CAP + p] = slot >> 1;
            g_rowgate[e * CAP + p] = g_slot_g[slot];
        }
    }
}

// ---------------------------------------------------------------------------
// GEMM1: 256x64(pair) tile, BK=16, 512 threads (16 warps, 4x4).
// Warp tile 64x16(pair). Conflict-free pitches, 2-stage double buffer.
// ---------------------------------------------------------------------------
#define PA1 264
#define PB1 72
#define NIT1 (DIM/BK)      // 64
#define SMEM1_BYTES ((8448 + 2304 + 2304 + 256) * 4)

__global__ __launch_bounds__(512, 1) void gemm1_kernel(const float* __restrict__ x,
                                                       const float* __restrict__ W1) {
    extern __shared__ unsigned sm1[];
    unsigned* As = sm1;                // [2][16][264]
    unsigned* B1 = sm1 + 8448;         // [2][16][72]
    unsigned* B2 = sm1 + 10752;        // [2][16][72]
    int* stok    = (int*)(sm1 + 13056);

    int e   = blockIdx.z;
    int cnt = g_count[e];
    int r0  = blockIdx.y * 256;
    if (r0 >= cnt) return;
    int n0  = blockIdx.x * 64;
    int tid = threadIdx.x;
    int lane = tid & 31, warp = tid >> 5;
    int gid = lane >> 2, tid4 = lane & 3;
    int warp_m = warp >> 2;      // 0..3 -> 64 rows each
    int warp_n = warp & 3;       // 0..3 -> 16 pair-cols each

    if (tid < 256) stok[tid] = g_row2tok[e * CAP + r0 + tid];
    __syncthreads();

    const float* W1e = W1 + (size_t)e * DIM * (2 * IDIM);

    // A loader: row arow, 8 consecutive floats at col acol
    int arow = tid >> 1;
    int acol = (tid & 1) * 8;
    const float* xrow = x + (size_t)stok[arow] * DIM + acol;

    // B loader: tid<256 -> B1, else B2; one float4
    int bsel = tid >> 8;
    int bidx = tid & 255;
    int bk   = bidx >> 4;
    int bn   = (bidx & 15) * 4;
    const float* bp0 = W1e + (size_t)bk * (2 * IDIM) + n0 + bsel * IDIM + bn;
    unsigned* Bown = bsel ? B2 : B1;

    float ar[8]; float4 br;
    {
        float4 t0 = *(const float4*)xrow;
        float4 t1 = *(const float4*)(xrow + 4);
        ar[0]=t0.x; ar[1]=t0.y; ar[2]=t0.z; ar[3]=t0.w;
        ar[4]=t1.x; ar[5]=t1.y; ar[6]=t1.z; ar[7]=t1.w;
        br = *(const float4*)bp0;
    }
    // store stage 0
    {
#pragma unroll
        for (int c = 0; c < 8; c++) As[(acol + c) * PA1 + arow] = f2tf32(ar[c]);
        uint4 bv; bv.x=f2tf32(br.x); bv.y=f2tf32(br.y); bv.z=f2tf32(br.z); bv.w=f2tf32(br.w);
        *(uint4*)&Bown[bk * PB1 + bn] = bv;
    }

    float c1[4][2][4], c2[4][2][4];
#pragma unroll
    for (int mt = 0; mt < 4; mt++)
#pragma unroll
        for (int nt = 0; nt < 2; nt++)
#pragma unroll
            for (int j = 0; j < 4; j++) { c1[mt][nt][j]=0.f; c2[mt][nt][j]=0.f; }

    for (int it = 0; it < NIT1; it++) {
        __syncthreads();
        int st = it & 1;
        bool more = (it + 1 < NIT1);
        float arn[8]; float4 brn;
        if (more) {
            const float* p = xrow + (it + 1) * BK;
            float4 t0 = *(const float4*)p;
            float4 t1 = *(const float4*)(p + 4);
            arn[0]=t0.x; arn[1]=t0.y; arn[2]=t0.z; arn[3]=t0.w;
            arn[4]=t1.x; arn[5]=t1.y; arn[6]=t1.z; arn[7]=t1.w;
            brn = *(const float4*)(bp0 + (size_t)(it + 1) * BK * (2 * IDIM));
        }

        const unsigned* Ast = As + st * (16 * PA1);
        const unsigned* B1t = B1 + st * (16 * PB1);
        const unsigned* B2t = B2 + st * (16 * PB1);
#pragma unroll
        for (int kk = 0; kk < BK; kk += 8) {
            unsigned a[4][4];
#pragma unroll
            for (int mt = 0; mt < 4; mt++) {
                int m = warp_m * 64 + mt * 16 + gid;
                const unsigned* p0 = Ast + (kk + tid4) * PA1;
                const unsigned* p4 = Ast + (kk + tid4 + 4) * PA1;
                a[mt][0] = p0[m]; a[mt][1] = p0[m + 8];
                a[mt][2] = p4[m]; a[mt][3] = p4[m + 8];
            }
#pragma unroll
            for (int nt = 0; nt < 2; nt++) {
                int n = warp_n * 16 + nt * 8 + gid;
                unsigned b10 = B1t[(kk + tid4) * PB1 + n];
                unsigned b11 = B1t[(kk + tid4 + 4) * PB1 + n];
                unsigned b20 = B2t[(kk + tid4) * PB1 + n];
                unsigned b21 = B2t[(kk + tid4 + 4) * PB1 + n];
#pragma unroll
                for (int mt = 0; mt < 4; mt++) {
                    mma_tf32(c1[mt][nt], a[mt], b10, b11);
                    mma_tf32(c2[mt][nt], a[mt], b20, b21);
                }
            }
        }

        if (more) {
            unsigned* Asw = As + (st ^ 1) * (16 * PA1);
#pragma unroll
            for (int c = 0; c < 8; c++) Asw[(acol + c) * PA1 + arow] = f2tf32(arn[c]);
            uint4 bv; bv.x=f2tf32(brn.x); bv.y=f2tf32(brn.y); bv.z=f2tf32(brn.z); bv.w=f2tf32(brn.w);
            *(uint4*)&Bown[(st ^ 1) * (16 * PB1) + bk * PB1 + bn] = bv;
        }
    }

    // epilogue: exact gelu(inp) * gate
#pragma unroll
    for (int mt = 0; mt < 4; mt++) {
#pragma unroll
        for (int half = 0; half < 2; half++) {
            int r = r0 + warp_m * 64 + mt * 16 + gid + half * 8;
            float* dst = g_hglu + ((size_t)(e * CAP + r)) * IDIM;
#pragma unroll
            for (int nt = 0; nt < 2; nt++) {
                float i0 = c1[mt][nt][2 * half + 0];
                float i1 = c1[mt][nt][2 * half + 1];
                float g0 = 0.5f * i0 * (1.0f + erff(i0 * 0.70710678118654752f));
                float g1 = 0.5f * i1 * (1.0f + erff(i1 * 0.70710678118654752f));
                float2 v;
                v.x = g0 * c2[mt][nt][2 * half + 0];
                v.y = g1 * c2[mt][nt][2 * half + 1];
                int col = n0 + warp_n * 16 + nt * 8 + 2 * tid4;
                *(float2*)(dst + col) = v;
            }
        }
    }
}

// ---------------------------------------------------------------------------
// GEMM2: 128x256 tile, BK=16, 512 threads (16 warps, 4x4).
// Warp tile 32x64. Conflict-free pitches, 2-stage double buffer.
// ---------------------------------------------------------------------------
#define PA2 136
#define PB2 264
#define NIT2 (IDIM/BK)     // 128
#define SMEM2_BYTES ((4352 + 8448) * 4)

__global__ __launch_bounds__(512, 1) void gemm2_kernel(const float* __restrict__ W2,
                                                       float* __restrict__ out) {
    extern __shared__ unsigned sm2[];
    unsigned* As = sm2;          // [2][16][136]
    unsigned* Bs = sm2 + 4352;   // [2][16][264]

    int e   = blockIdx.z;
    int cnt = g_count[e];
    int r0  = blockIdx.y * 128;
    if (r0 >= cnt) return;
    int n0  = blockIdx.x * 256;
    int tid = threadIdx.x;
    int lane = tid & 31, warp = tid >> 5;
    int gid = lane >> 2, tid4 = lane & 3;
    int warp_m = warp >> 2;      // 0..3 -> 32 rows
    int warp_n = warp & 3;       // 0..3 -> 64 cols

    const float* W2e = W2 + (size_t)e * IDIM * DIM;

    // A loader: one float4 per thread
    int arow = (tid >> 1) & 127;
    int akq  = (tid & 1) + 2 * (tid >> 8);      // float4 index 0..3
    const float* ap0 = g_hglu + ((size_t)e * CAP + r0 + arow) * IDIM + akq * 4;

    // B loader: two float4 per thread
    int bk0 = tid >> 6;              // wait: recomputed below per f4
    (void)bk0;
    int f4a = tid, f4b = tid + 512;
    int bka = f4a >> 6, bna = (f4a & 63) * 4;
    int bkb = f4b >> 6, bnb = (f4b & 63) * 4;
    const float* bpa = W2e + (size_t)bka * DIM + n0 + bna;
    const float* bpb = W2e + (size_t)bkb * DIM + n0 + bnb;

    float4 arv, brv0, brv1;
    arv  = *(const float4*)ap0;
    brv0 = *(const float4*)bpa;
    brv1 = *(const float4*)bpb;
    {
#pragma unroll
        for (int c = 0; c < 4; c++) {
            float v = c == 0 ? arv.x : c == 1 ? arv.y : c == 2 ? arv.z : arv.w;
            As[(akq * 4 + c) * PA2 + arow] = f2tf32(v);
        }
        uint4 b0; b0.x=f2tf32(brv0.x); b0.y=f2tf32(brv0.y); b0.z=f2tf32(brv0.z); b0.w=f2tf32(brv0.w);
        uint4 b1; b1.x=f2tf32(brv1.x); b1.y=f2tf32(brv1.y); b1.z=f2tf32(brv1.z); b1.w=f2tf32(brv1.w);
        *(uint4*)&Bs[bka * PB2 + bna] = b0;
        *(uint4*)&Bs[bkb * PB2 + bnb] = b1;
    }

    float c[2][8][4];
#pragma unroll
    for (int mt = 0; mt < 2; mt++)
#pragma unroll
        for (int nt = 0; nt < 8; nt++)
#pragma unroll
            for (int j = 0; j < 4; j++) c[mt][nt][j] = 0.f;

    for (int it = 0; it < NIT2; it++) {
        __syncthreads();
        int st = it & 1;
        bool more = (it + 1 < NIT2);
        float4 arn, brn0, brn1;
        if (more) {
            int k0 = (it + 1) * BK;
            arn  = *(const float4*)(ap0 + k0);
            brn0 = *(const float4*)(bpa + (size_t)k0 * DIM);
            brn1 = *(const float4*)(bpb + (size_t)k0 * DIM);
        }

        const unsigned* Ast = As + st * (16 * PA2);
        const unsigned* Bst = Bs + st * (16 * PB2);
#pragma unroll
        for (int kk = 0; kk < BK; kk += 8) {
            unsigned a[2][4];
#pragma unroll
            for (int mt = 0; mt < 2; mt++) {
                int m = warp_m * 32 + mt * 16 + gid;
                const unsigned* p0 = Ast + (kk + tid4) * PA2;
                const unsigned* p4 = Ast + (kk + tid4 + 4) * PA2;
                a[mt][0] = p0[m]; a[mt][1] = p0[m + 8];
                a[mt][2] = p4[m]; a[mt][3] = p4[m + 8];
            }
#pragma unroll
            for (int nt = 0; nt < 8; nt++) {
                int n = warp_n * 64 + nt * 8 + gid;
                unsigned b0 = Bst[(kk + tid4) * PB2 + n];
                unsigned b1 = Bst[(kk + tid4 + 4) * PB2 + n];
#pragma unroll
                for (int mt = 0; mt < 2; mt++)
                    mma_tf32(c[mt][nt], a[mt], b0, b1);
            }
        }

        if (more) {
            unsigned* Asw = As + (st ^ 1) * (16 * PA2);
            unsigned* Bsw = Bs + (st ^ 1) * (16 * PB2);
#pragma unroll
            for (int cc = 0; cc < 4; cc++) {
                float v = cc == 0 ? arn.x : cc == 1 ? arn.y : cc == 2 ? arn.z : arn.w;
                Asw[(akq * 4 + cc) * PA2 + arow] = f2tf32(v);
            }
            uint4 b0; b0.x=f2tf32(brn0.x); b0.y=f2tf32(brn0.y); b0.z=f2tf32(brn0.z); b0.w=f2tf32(brn0.w);
            uint4 b1; b1.x=f2tf32(brn1.x); b1.y=f2tf32(brn1.y); b1.z=f2tf32(brn1.z); b1.w=f2tf32(brn1.w);
            *(uint4*)&Bsw[bka * PB2 + bna] = b0;
            *(uint4*)&Bsw[bkb * PB2 + bnb] = b1;
        }
    }

    // gate-weighted scatter
#pragma unroll
    for (int mt = 0; mt < 2; mt++) {
#pragma unroll
        for (int half = 0; half < 2; half++) {
            int r = r0 + warp_m * 32 + mt * 16 + gid + half * 8;
            if (r < cnt) {
                int tok   = g_row2tok[e * CAP + r];
                float gte = g_rowgate[e * CAP + r];
                float* op = out + (size_t)tok * DIM + n0 + warp_n * 64 + 2 * tid4;
#pragma unroll
                for (int nt = 0; nt < 8; nt++) {
                    float v0 = gte * c[mt][nt][2 * half + 0];
                    float v1 = gte * c[mt][nt][2 * half + 1];
                    asm volatile("red.global.add.v2.f32 [%0], {%1, %2};"
                                 :: "l"(op + nt * 8), "f"(v0), "f"(v1) : "memory");
                }
            }
        }
    }
}

// ---------------------------------------------------------------------------
extern "C" void kernel_launch(void* const* d_in, const int* in_sizes, int n_in,
                              void* d_out, int out_size) {
    const float* x  = (const float*)d_in[0];
    const float* Wg = (const float*)d_in[1];
    const float* W1 = (const float*)d_in[2];
    const float* W2 = (const float*)d_in[3];
    float* out = (float*)d_out;

    cudaFuncSetAttribute(gemm1_kernel, cudaFuncAttributeMaxDynamicSharedMemorySize, SMEM1_BYTES);
    cudaFuncSetAttribute(gemm2_kernel, cudaFuncAttributeMaxDynamicSharedMemorySize, SMEM2_BYTES);

    cudaMemsetAsync(out, 0, (size_t)NTOK * DIM * sizeof(float));

    router_kernel<<<NTOK / 8, 256>>>(x, Wg);
    scan_kernel<<<1, 256>>>();

    dim3 g1(IDIM / 64, CAP / 256, NEXP);   // (32, 5, 8)
    gemm1_kernel<<<g1, 512, SMEM1_BYTES>>>(x, W1);

    dim3 g2(DIM / 256, CAP / 128, NEXP);   // (4, 10, 8)
    gemm2_kernel<<<g2, 512, SMEM2_BYTES>>>(W2, out);
}

// round 5
// speedup vs baseline: 3.1818x; 1.1936x over previous
#include <cuda_runtime.h>
#include <math.h>

// Problem constants
#define NTOK 4096
#define DIM  1024
#define NEXP 8
#define TOPK 2
#define IDIM 2048
#define CAP  1280
#define NSLOT (NTOK*TOPK)

// Scratch (static; no cudaMalloc allowed)
__device__ float    g_hglu[(size_t)NEXP * CAP * IDIM];      // 84 MB (holds tf32 bit patterns)
__device__ unsigned g_xc [(size_t)NTOK * DIM];              // 16 MB  x in tf32
__device__ unsigned g_w1c[(size_t)NEXP * DIM * 2 * IDIM];   // 128 MB W1 in tf32
__device__ unsigned g_w2c[(size_t)NEXP * IDIM * DIM];       // 64 MB  W2 in tf32
__device__ int   g_row2tok[NEXP * CAP];
__device__ float g_rowgate[NEXP * CAP];
__device__ int   g_count[NEXP];
__device__ int   g_slot_e[NSLOT];
__device__ float g_slot_g[NSLOT];

__device__ __forceinline__ unsigned f2tf32(float f) {
    unsigned r;
    asm("cvt.rna.tf32.f32 %0, %1;" : "=r"(r) : "f"(f));
    return r;
}

__device__ __forceinline__ void mma_tf32(float* c, const unsigned* a, unsigned b0, unsigned b1) {
    asm volatile(
        "mma.sync.aligned.m16n8k8.row.col.f32.tf32.tf32.f32 "
        "{%0,%1,%2,%3}, {%4,%5,%6,%7}, {%8,%9}, {%0,%1,%2,%3};\n"
        : "+f"(c[0]), "+f"(c[1]), "+f"(c[2]), "+f"(c[3])
        : "r"(a[0]), "r"(a[1]), "r"(a[2]), "r"(a[3]), "r"(b0), "r"(b1));
}

__device__ __forceinline__ void cpa16(unsigned smem_addr, const void* gptr) {
    asm volatile("cp.async.cg.shared.global [%0], [%1], 16;"
                 :: "r"(smem_addr), "l"(gptr) : "memory");
}

// ---------------------------------------------------------------------------
// Pre-convert f32 -> tf32 bits (vectorized)
// ---------------------------------------------------------------------------
__global__ void cvt_kernel(const float* __restrict__ src, unsigned* __restrict__ dst, int n4) {
    int i = blockIdx.x * blockDim.x + threadIdx.x;
    if (i < n4) {
        float4 v = ((const float4*)src)[i];
        uint4 o;
        o.x = f2tf32(v.x); o.y = f2tf32(v.y); o.z = f2tf32(v.z); o.w = f2tf32(v.w);
        ((uint4*)dst)[i] = o;
    }
}

// ---------------------------------------------------------------------------
// Router
// ---------------------------------------------------------------------------
__global__ void router_kernel(const float* __restrict__ x,
                              const float* __restrict__ Wg) {
    int warp = (blockIdx.x * blockDim.x + threadIdx.x) >> 5;
    int lane = threadIdx.x & 31;
    if (warp >= NTOK) return;
    const float* xr = x + (size_t)warp * DIM;
    float acc[NEXP];
#pragma unroll
    for (int e = 0; e < NEXP; e++) acc[e] = 0.f;
    for (int i = lane; i < DIM; i += 32) {
        float xv = __ldg(xr + i);
#pragma unroll
        for (int e = 0; e < NEXP; e++) acc[e] += xv * __ldg(Wg + e * DIM + i);
    }
#pragma unroll
    for (int e = 0; e < NEXP; e++) {
#pragma unroll
        for (int off = 16; off > 0; off >>= 1)
            acc[e] += __shfl_xor_sync(0xffffffffu, acc[e], off);
    }
    if (lane == 0) {
        int i0 = 0; float v0 = acc[0];
#pragma unroll
        for (int e = 1; e < NEXP; e++) if (acc[e] > v0) { v0 = acc[e]; i0 = e; }
        int i1 = -1; float v1 = -1e30f;
#pragma unroll
        for (int e = 0; e < NEXP; e++)
            if (e != i0 && acc[e] > v1) { v1 = acc[e]; i1 = e; }
        float e0 = expf(v0 - v0), e1 = expf(v1 - v0);
        float inv = 1.0f / (e0 + e1);
        g_slot_e[2 * warp + 0] = i0; g_slot_g[2 * warp + 0] = e0 * inv;
        g_slot_e[2 * warp + 1] = i1; g_slot_g[2 * warp + 1] = e1 * inv;
    }
}

// ---------------------------------------------------------------------------
// Capacity scan (single block; slot order token-major then k)
// ---------------------------------------------------------------------------
__global__ void scan_kernel() {
    __shared__ int smc[256][NEXP];
    int tid = threadIdx.x;
    for (int i = tid; i < NEXP * CAP; i += 256) {
        g_row2tok[i] = 0;
        g_rowgate[i] = 0.f;
    }
    const int PER = NSLOT / 256;
    int s0 = tid * PER;
    int le[PER];
    int c[NEXP];
#pragma unroll
    for (int e = 0; e < NEXP; e++) c[e] = 0;
#pragma unroll
    for (int j = 0; j < PER; j++) {
        int e = g_slot_e[s0 + j];
        le[j] = e;
        c[e]++;
    }
#pragma unroll
    for (int e = 0; e < NEXP; e++) smc[tid][e] = c[e];
    __syncthreads();
    if (tid < NEXP) {
        int run = 0;
        for (int t = 0; t < 256; t++) {
            int v = smc[t][tid];
            smc[t][tid] = run;
            run += v;
        }
        g_count[tid] = run < CAP ? run : CAP;
    }
    __syncthreads();
    int off[NEXP];
#pragma unroll
    for (int e = 0; e < NEXP; e++) off[e] = smc[tid][e];
#pragma unroll
    for (int j = 0; j < PER; j++) {
        int e = le[j];
        int p = off[e]++;
        if (p < CAP) {
            int slot = s0 + j;
            g_row2tok[e * CAP + p] = slot >> 1;
            g_rowgate[e * CAP + p] = g_slot_g[slot];
        }
    }
}

// ---------------------------------------------------------------------------
// GEMM1: 256 rows x 64 GLU-cols (both halves), BK=32, 512 thr, 4-stage cp.async.
// A row-major pitch 36 (bank-perfect), B1/B2 k-major pitch 72.
// ---------------------------------------------------------------------------
#define G1_PA 36
#define G1_PB 72
#define G1_ASZ (256 * G1_PA)            // 9216 u32
#define G1_BSZ (32 * G1_PB)             // 2304 u32
#define G1_STG (G1_ASZ + 2 * G1_BSZ)    // 13824 u32
#define G1_NIT 32
#define SMEM1_BYTES ((4 * G1_STG + 256) * 4)   // 222208

__global__ __launch_bounds__(512, 1) void gemm1_kernel(const unsigned* __restrict__ xc,
                                                       const unsigned* __restrict__ w1c) {
    extern __shared__ unsigned sm1[];
    int* stok = (int*)(sm1 + 4 * G1_STG);

    int e   = blockIdx.z;
    int cnt = g_count[e];
    int r0  = blockIdx.y * 256;
    if (r0 >= cnt) return;
    int n0  = blockIdx.x * 64;
    int tid = threadIdx.x;
    int lane = tid & 31, warp = tid >> 5;
    int gid = lane >> 2, tid4 = lane & 3;
    int warp_m = warp >> 2, warp_n = warp & 3;

    if (tid < 256) stok[tid] = g_row2tok[e * CAP + r0 + tid];
    __syncthreads();

    unsigned sbase = (unsigned)__cvta_generic_to_shared(sm1);

    // A loader: 4 chunks/thread (256 rows x 8 chunks of 4 floats)
    const unsigned* asrc[4]; unsigned adst[4];
#pragma unroll
    for (int j = 0; j < 4; j++) {
        int c = tid + 512 * j;
        int row = c >> 3, kc = c & 7;
        asrc[j] = xc + (size_t)stok[row] * DIM + kc * 4;
        adst[j] = (unsigned)(row * G1_PA + kc * 4) * 4;
    }
    // B loader: 2 chunks/thread (2 mats x 32 k x 16 chunks = 1024 chunks)
    const unsigned* bsrc[2]; unsigned bdst[2];
#pragma unroll
    for (int j = 0; j < 2; j++) {
        int c = tid + 512 * j;
        int mat = c >> 9, k = (c >> 4) & 31, nc = c & 15;
        bsrc[j] = w1c + (size_t)e * DIM * 2 * IDIM + (size_t)k * (2 * IDIM) + n0 + mat * IDIM + nc * 4;
        bdst[j] = (unsigned)(G1_ASZ + mat * G1_BSZ + k * G1_PB + nc * 4) * 4;
    }

    // prefill 3 stages
#pragma unroll
    for (int s = 0; s < 3; s++) {
        unsigned sb = sbase + s * (G1_STG * 4);
        int k0 = s * 32;
#pragma unroll
        for (int j = 0; j < 4; j++) cpa16(sb + adst[j], asrc[j] + k0);
#pragma unroll
        for (int j = 0; j < 2; j++) cpa16(sb + bdst[j], bsrc[j] + (size_t)k0 * (2 * IDIM));
        asm volatile("cp.async.commit_group;" ::: "memory");
    }

    float c1[4][2][4], c2[4][2][4];
#pragma unroll
    for (int mt = 0; mt < 4; mt++)
#pragma unroll
        for (int nt = 0; nt < 2; nt++)
#pragma unroll
            for (int j = 0; j < 4; j++) { c1[mt][nt][j] = 0.f; c2[mt][nt][j] = 0.f; }

    for (int it = 0; it < G1_NIT; it++) {
        asm volatile("cp.async.wait_group 2;" ::: "memory");
        __syncthreads();
        int st = it & 3;
        const unsigned* Ast = sm1 + st * G1_STG;
        const unsigned* B1t = Ast + G1_ASZ;
        const unsigned* B2t = B1t + G1_BSZ;
#pragma unroll
        for (int kk = 0; kk < 32; kk += 8) {
            unsigned a[4][4];
#pragma unroll
            for (int mt = 0; mt < 4; mt++) {
                int m = warp_m * 64 + mt * 16 + gid;
                a[mt][0] = Ast[m * G1_PA + kk + tid4];
                a[mt][1] = Ast[(m + 8) * G1_PA + kk + tid4];
                a[mt][2] = Ast[m * G1_PA + kk + tid4 + 4];
                a[mt][3] = Ast[(m + 8) * G1_PA + kk + tid4 + 4];
            }
#pragma unroll
            for (int nt = 0; nt < 2; nt++) {
                int n = warp_n * 16 + nt * 8 + gid;
                unsigned b10 = B1t[(kk + tid4) * G1_PB + n];
                unsigned b11 = B1t[(kk + tid4 + 4) * G1_PB + n];
                unsigned b20 = B2t[(kk + tid4) * G1_PB + n];
                unsigned b21 = B2t[(kk + tid4 + 4) * G1_PB + n];
#pragma unroll
                for (int mt = 0; mt < 4; mt++) {
                    mma_tf32(c1[mt][nt], a[mt], b10, b11);
                    mma_tf32(c2[mt][nt], a[mt], b20, b21);
                }
            }
        }
        if (it + 3 < G1_NIT) {
            unsigned sb = sbase + ((it + 3) & 3) * (G1_STG * 4);
            int k0 = (it + 3) * 32;
#pragma unroll
            for (int j = 0; j < 4; j++) cpa16(sb + adst[j], asrc[j] + k0);
#pragma unroll
            for (int j = 0; j < 2; j++) cpa16(sb + bdst[j], bsrc[j] + (size_t)k0 * (2 * IDIM));
        }
        asm volatile("cp.async.commit_group;" ::: "memory");
    }

    // epilogue: exact gelu(inp) * gate, stored as tf32 bit pattern
#pragma unroll
    for (int mt = 0; mt < 4; mt++) {
#pragma unroll
        for (int half = 0; half < 2; half++) {
            int r = r0 + warp_m * 64 + mt * 16 + gid + half * 8;
            float* dst = g_hglu + ((size_t)(e * CAP + r)) * IDIM;
#pragma unroll
            for (int nt = 0; nt < 2; nt++) {
                float i0 = c1[mt][nt][2 * half + 0];
                float i1 = c1[mt][nt][2 * half + 1];
                float g0 = 0.5f * i0 * (1.0f + erff(i0 * 0.70710678118654752f));
                float g1 = 0.5f * i1 * (1.0f + erff(i1 * 0.70710678118654752f));
                float2 v;
                v.x = __uint_as_float(f2tf32(g0 * c2[mt][nt][2 * half + 0]));
                v.y = __uint_as_float(f2tf32(g1 * c2[mt][nt][2 * half + 1]));
                int col = n0 + warp_n * 16 + nt * 8 + 2 * tid4;
                *(float2*)(dst + col) = v;
            }
        }
    }
}

// ---------------------------------------------------------------------------
// GEMM2: 128 rows x 256 out-cols, BK=32, 512 thr, 4-stage cp.async.
// A row-major pitch 36, B k-major pitch 264. Gate-weighted scatter epilogue.
// ---------------------------------------------------------------------------
#define G2_PA 36
#define G2_PB 264
#define G2_ASZ (128 * G2_PA)         // 4608 u32
#define G2_BSZ (32 * G2_PB)          // 8448 u32
#define G2_STG (G2_ASZ + G2_BSZ)     // 13056 u32
#define G2_NIT 64
#define SMEM2_BYTES (4 * G2_STG * 4) // 208896

__global__ __launch_bounds__(512, 1) void gemm2_kernel(const unsigned* __restrict__ w2c,
                                                       float* __restrict__ out) {
    extern __shared__ unsigned sm2[];

    int e   = blockIdx.z;
    int cnt = g_count[e];
    int r0  = blockIdx.y * 128;
    if (r0 >= cnt) return;
    int n0  = blockIdx.x * 256;
    int tid = threadIdx.x;
    int lane = tid & 31, warp = tid >> 5;
    int gid = lane >> 2, tid4 = lane & 3;
    int warp_m = warp >> 2, warp_n = warp & 3;

    unsigned sbase = (unsigned)__cvta_generic_to_shared(sm2);
    const unsigned* hbase = (const unsigned*)g_hglu + (size_t)e * CAP * IDIM;
    const unsigned* w2e   = w2c + (size_t)e * IDIM * DIM;

    // A loader: 2 chunks/thread (128 rows x 8 chunks)
    const unsigned* asrc[2]; unsigned adst[2];
#pragma unroll
    for (int j = 0; j < 2; j++) {
        int c = tid + 512 * j;
        int row = c >> 3, kc = c & 7;
        asrc[j] = hbase + (size_t)(r0 + row) * IDIM + kc * 4;
        adst[j] = (unsigned)(row * G2_PA + kc * 4) * 4;
    }
    // B loader: 4 chunks/thread (32 k x 64 chunks)
    const unsigned* bsrc[4]; unsigned bdst[4];
#pragma unroll
    for (int j = 0; j < 4; j++) {
        int c = tid + 512 * j;
        int k = c >> 6, nc = c & 63;
        bsrc[j] = w2e + (size_t)k * DIM + n0 + nc * 4;
        bdst[j] = (unsigned)(G2_ASZ + k * G2_PB + nc * 4) * 4;
    }

    // prefill 3 stages
#pragma unroll
    for (int s = 0; s < 3; s++) {
        unsigned sb = sbase + s * (G2_STG * 4);
        int k0 = s * 32;
#pragma unroll
        for (int j = 0; j < 2; j++) cpa16(sb + adst[j], asrc[j] + k0);
#pragma unroll
        for (int j = 0; j < 4; j++) cpa16(sb + bdst[j], bsrc[j] + (size_t)k0 * DIM);
        asm volatile("cp.async.commit_group;" ::: "memory");
    }

    float c[2][8][4];
#pragma unroll
    for (int mt = 0; mt < 2; mt++)
#pragma unroll
        for (int nt = 0; nt < 8; nt++)
#pragma unroll
            for (int j = 0; j < 4; j++) c[mt][nt][j] = 0.f;

    for (int it = 0; it < G2_NIT; it++) {
        asm volatile("cp.async.wait_group 2;" ::: "memory");
        __syncthreads();
        int st = it & 3;
        const unsigned* Ast = sm2 + st * G2_STG;
        const unsigned* Bst = Ast + G2_ASZ;
#pragma unroll
        for (int kk = 0; kk < 32; kk += 8) {
            unsigned a[2][4];
#pragma unroll
            for (int mt = 0; mt < 2; mt++) {
                int m = warp_m * 32 + mt * 16 + gid;
                a[mt][0] = Ast[m * G2_PA + kk + tid4];
                a[mt][1] = Ast[(m + 8) * G2_PA + kk + tid4];
                a[mt][2] = Ast[m * G2_PA + kk + tid4 + 4];
                a[mt][3] = Ast[(m + 8) * G2_PA + kk + tid4 + 4];
            }
#pragma unroll
            for (int nt = 0; nt < 8; nt++) {
                int n = warp_n * 64 + nt * 8 + gid;
                unsigned b0 = Bst[(kk + tid4) * G2_PB + n];
                unsigned b1 = Bst[(kk + tid4 + 4) * G2_PB + n];
#pragma unroll
                for (int mt = 0; mt < 2; mt++)
                    mma_tf32(c[mt][nt], a[mt], b0, b1);
            }
        }
        if (it + 3 < G2_NIT) {
            unsigned sb = sbase + ((it + 3) & 3) * (G2_STG * 4);
            int k0 = (it + 3) * 32;
#pragma unroll
            for (int j = 0; j < 2; j++) cpa16(sb + adst[j], asrc[j] + k0);
#pragma unroll
            for (int j = 0; j < 4; j++) cpa16(sb + bdst[j], bsrc[j] + (size_t)k0 * DIM);
        }
        asm volatile("cp.async.commit_group;" ::: "memory");
    }

    // gate-weighted scatter
#pragma unroll
    for (int mt = 0; mt < 2; mt++) {
#pragma unroll
        for (int half = 0; half < 2; half++) {
            int r = r0 + warp_m * 32 + mt * 16 + gid + half * 8;
            if (r < cnt) {
                int tok   = g_row2tok[e * CAP + r];
                float gte = g_rowgate[e * CAP + r];
                float* op = out + (size_t)tok * DIM + n0 + warp_n * 64 + 2 * tid4;
#pragma unroll
                for (int nt = 0; nt < 8; nt++) {
                    float v0 = gte * c[mt][nt][2 * half + 0];
                    float v1 = gte * c[mt][nt][2 * half + 1];
                    asm volatile("red.global.add.v2.f32 [%0], {%1, %2};"
                                 :: "l"(op + nt * 8), "f"(v0), "f"(v1) : "memory");
                }
            }
        }
    }
}

// ---------------------------------------------------------------------------
extern "C" void kernel_launch(void* const* d_in, const int* in_sizes, int n_in,
                              void* d_out, int out_size) {
    const float* x  = (const float*)d_in[0];
    const float* Wg = (const float*)d_in[1];
    const float* W1 = (const float*)d_in[2];
    const float* W2 = (const float*)d_in[3];
    float* out = (float*)d_out;

    cudaFuncSetAttribute(gemm1_kernel, cudaFuncAttributeMaxDynamicSharedMemorySize, SMEM1_BYTES);
    cudaFuncSetAttribute(gemm2_kernel, cudaFuncAttributeMaxDynamicSharedMemorySize, SMEM2_BYTES);

    unsigned *xc, *w1c, *w2c;
    cudaGetSymbolAddress((void**)&xc,  g_xc);
    cudaGetSymbolAddress((void**)&w1c, g_w1c);
    cudaGetSymbolAddress((void**)&w2c, g_w2c);

    cudaMemsetAsync(out, 0, (size_t)NTOK * DIM * sizeof(float));

    // Pre-convert to tf32
    cvt_kernel<<<(NTOK * DIM / 4 + 255) / 256, 256>>>(x, xc, NTOK * DIM / 4);
    cvt_kernel<<<(NEXP * DIM * 2 * IDIM / 4 + 255) / 256, 256>>>(W1, w1c, NEXP * DIM * 2 * IDIM / 4);
    cvt_kernel<<<(NEXP * IDIM * DIM / 4 + 255) / 256, 256>>>(W2, w2c, NEXP * IDIM * DIM / 4);

    router_kernel<<<NTOK / 8, 256>>>(x, Wg);
    scan_kernel<<<1, 256>>>();

    dim3 g1(IDIM / 64, CAP / 256, NEXP);   // (32, 5, 8)
    gemm1_kernel<<<g1, 512, SMEM1_BYTES>>>(xc, w1c);

    dim3 g2(DIM / 256, CAP / 128, NEXP);   // (4, 10, 8)
    gemm2_kernel<<<g2, 512, SMEM2_BYTES>>>(w2c, out);
}

// round 9
// speedup vs baseline: 3.3118x; 1.0409x over previous
#include <cuda_runtime.h>
#include <math.h>

// Problem constants
#define NTOK 4096
#define DIM  1024
#define NEXP 8
#define IDIM 2048
#define CAP  1280
#define NSLOT (NTOK*2)

// Scratch (static; no cudaMalloc allowed)
__device__ float    g_hglu[(size_t)NEXP * CAP * IDIM];        // 84 MB (tf32-rounded f32)
__device__ unsigned g_xc [(size_t)NTOK * DIM];                // x tf32, [tok][k]
__device__ unsigned g_w1t[(size_t)NEXP * 2 * IDIM * DIM];     // W1^T tf32, [e][n][k]
__device__ unsigned g_w2t[(size_t)NEXP * DIM * IDIM];         // W2^T tf32, [e][n][k]
__device__ int   g_row2tok[NEXP * CAP];
__device__ float g_rowgate[NEXP * CAP];
__device__ int   g_count[NEXP];
__device__ int   g_slot_e[NSLOT];
__device__ float g_slot_g[NSLOT];

__device__ __forceinline__ unsigned f2tf32(float f) {
    unsigned r;
    asm("cvt.rna.tf32.f32 %0, %1;" : "=r"(r) : "f"(f));
    return r;
}
__device__ __forceinline__ void mma_tf32(float* c, const unsigned* a, unsigned b0, unsigned b1) {
    asm volatile(
        "mma.sync.aligned.m16n8k8.row.col.f32.tf32.tf32.f32 "
        "{%0,%1,%2,%3}, {%4,%5,%6,%7}, {%8,%9}, {%0,%1,%2,%3};\n"
        : "+f"(c[0]), "+f"(c[1]), "+f"(c[2]), "+f"(c[3])
        : "r"(a[0]), "r"(a[1]), "r"(a[2]), "r"(a[3]), "r"(b0), "r"(b1));
}
__device__ __forceinline__ void cpa16(unsigned smem_addr, const void* gptr) {
    asm volatile("cp.async.cg.shared.global [%0], [%1], 16;"
                 :: "r"(smem_addr), "l"(gptr) : "memory");
}
__device__ __forceinline__ void ldsm4(unsigned* r, unsigned addr) {
    asm volatile("ldmatrix.sync.aligned.m8n8.x4.shared.b16 {%0,%1,%2,%3}, [%4];"
                 : "=r"(r[0]), "=r"(r[1]), "=r"(r[2]), "=r"(r[3]) : "r"(addr));
}
__device__ __forceinline__ unsigned smem_u32(const void* p) {
    unsigned a;
    asm("{ .reg .u64 t; cvta.to.shared.u64 t, %1; cvt.u32.u64 %0, t; }" : "=r"(a) : "l"(p));
    return a;
}

// ---------------------------------------------------------------------------
// Pre-convert: x -> tf32; W -> transpose [e][n][k] + tf32
// ---------------------------------------------------------------------------
__global__ void cvt_kernel(const float* __restrict__ src, unsigned* __restrict__ dst, int n4) {
    int i = blockIdx.x * blockDim.x + threadIdx.x;
    if (i < n4) {
        float4 v = ((const float4*)src)[i];
        uint4 o;
        o.x = f2tf32(v.x); o.y = f2tf32(v.y); o.z = f2tf32(v.z); o.w = f2tf32(v.w);
        ((uint4*)dst)[i] = o;
    }
}
__global__ void cvtT_kernel(const float* __restrict__ src, unsigned* __restrict__ dst,
                            int R, int C) {
    __shared__ float t[32][33];
    int e = blockIdx.z;
    const float* s = src + (size_t)e * R * C;
    unsigned* d = dst + (size_t)e * R * C;
    int c0 = blockIdx.x * 32, r0 = blockIdx.y * 32;
#pragma unroll
    for (int j = 0; j < 32; j += 8)
        t[threadIdx.y + j][threadIdx.x] = s[(size_t)(r0 + threadIdx.y + j) * C + c0 + threadIdx.x];
    __syncthreads();
#pragma unroll
    for (int j = 0; j < 32; j += 8)
        d[(size_t)(c0 + threadIdx.y + j) * R + r0 + threadIdx.x] = f2tf32(t[threadIdx.x][threadIdx.y + j]);
}

// ---------------------------------------------------------------------------
// Router
// ---------------------------------------------------------------------------
__global__ void router_kernel(const float* __restrict__ x,
                              const float* __restrict__ Wg) {
    int warp = (blockIdx.x * blockDim.x + threadIdx.x) >> 5;
    int lane = threadIdx.x & 31;
    if (warp >= NTOK) return;
    const float* xr = x + (size_t)warp * DIM;
    float acc[NEXP];
#pragma unroll
    for (int e = 0; e < NEXP; e++) acc[e] = 0.f;
    for (int i = lane; i < DIM; i += 32) {
        float xv = __ldg(xr + i);
#pragma unroll
        for (int e = 0; e < NEXP; e++) acc[e] += xv * __ldg(Wg + e * DIM + i);
    }
#pragma unroll
    for (int e = 0; e < NEXP; e++) {
#pragma unroll
        for (int off = 16; off > 0; off >>= 1)
            acc[e] += __shfl_xor_sync(0xffffffffu, acc[e], off);
    }
    if (lane == 0) {
        int i0 = 0; float v0 = acc[0];
#pragma unroll
        for (int e = 1; e < NEXP; e++) if (acc[e] > v0) { v0 = acc[e]; i0 = e; }
        int i1 = -1; float v1 = -1e30f;
#pragma unroll
        for (int e = 0; e < NEXP; e++)
            if (e != i0 && acc[e] > v1) { v1 = acc[e]; i1 = e; }
        float e0 = expf(v0 - v0), e1 = expf(v1 - v0);
        float inv = 1.0f / (e0 + e1);
        g_slot_e[2 * warp + 0] = i0; g_slot_g[2 * warp + 0] = e0 * inv;
        g_slot_e[2 * warp + 1] = i1; g_slot_g[2 * warp + 1] = e1 * inv;
    }
}

// ---------------------------------------------------------------------------
// Capacity scan
// ---------------------------------------------------------------------------
__global__ void scan_kernel() {
    __shared__ int smc[256][NEXP];
    int tid = threadIdx.x;
    for (int i = tid; i < NEXP * CAP; i += 256) {
        g_row2tok[i] = 0;
        g_rowgate[i] = 0.f;
    }
    const int PER = NSLOT / 256;
    int s0 = tid * PER;
    int le[PER];
    int c[NEXP];
#pragma unroll
    for (int e = 0; e < NEXP; e++) c[e] = 0;
#pragma unroll
    for (int j = 0; j < PER; j++) {
        int e = g_slot_e[s0 + j];
        le[j] = e;
        c[e]++;
    }
#pragma unroll
    for (int e = 0; e < NEXP; e++) smc[tid][e] = c[e];
    __syncthreads();
    if (tid < NEXP) {
        int run = 0;
        for (int t = 0; t < 256; t++) {
            int v = smc[t][tid];
            smc[t][tid] = run;
            run += v;
        }
        g_count[tid] = run < CAP ? run : CAP;
    }
    __syncthreads();
    int off[NEXP];
#pragma unroll
    for (int e = 0; e < NEXP; e++) off[e] = smc[tid][e];
#pragma unroll
    for (int j = 0; j < PER; j++) {
        int e = le[j];
        int p = off[e]++;
        if (p < CAP) {
            int slot = s0 + j;
            g_row2tok[e * CAP + p] = slot >> 1;
            g_rowgate[e * CAP + p] = g_slot_g[slot];
        }
    }
}

// ---------------------------------------------------------------------------
// GEMM1: block 128m x 64 pair-cols, 256 thr, 8 warps (2x4), warp tile 64x16pair.
// A [128][32] pitch 36, B1/B2 n-major [64][32] pitch 36. ldmatrix fragments.
// 4-stage cp.async.
// ---------------------------------------------------------------------------
#define PITCH 36
#define G1_ASZ (128 * PITCH)             // 4608 u32
#define G1_BSZ (64 * PITCH)              // 2304 u32
#define G1_STG (G1_ASZ + 2 * G1_BSZ)     // 9216 u32
#define G1_NIT (DIM / 32)                // 32
#define SMEM1_BYTES ((4 * G1_STG + 128) * 4)

__global__ __launch_bounds__(256, 1) void gemm1_kernel(const unsigned* __restrict__ xc,
                                                       const unsigned* __restrict__ w1t) {
    extern __shared__ unsigned sm1[];
    int* stok = (int*)(sm1 + 4 * G1_STG);

    int e   = blockIdx.z;
    int cnt = g_count[e];
    int r0  = blockIdx.y * 128;
    if (r0 >= cnt) return;
    int n0  = blockIdx.x * 64;
    int tid = threadIdx.x;
    int lane = tid & 31, warp = tid >> 5;
    int gid = lane >> 2, tid4 = lane & 3;
    int warp_m = warp >> 2;    // 0..1
    int warp_n = warp & 3;     // 0..3

    if (tid < 128) stok[tid] = g_row2tok[e * CAP + r0 + tid];
    __syncthreads();

    unsigned sbase = smem_u32(sm1);

    // Loaders: A 4 chunks/thread (128 rows x 8), B 4 chunks/thread (128 rows x 8)
    const unsigned* asrc[4]; unsigned adst[4];
#pragma unroll
    for (int j = 0; j < 4; j++) {
        int c = tid + 256 * j;
        int row = c >> 3, ch = c & 7;
        asrc[j] = xc + (size_t)stok[row] * DIM + ch * 4;
        adst[j] = (unsigned)(row * PITCH + ch * 4) * 4;
    }
    const unsigned* bsrc[4]; unsigned bdst[4];
#pragma unroll
    for (int j = 0; j < 4; j++) {
        int c = tid + 256 * j;
        int r = c >> 3, ch = c & 7;                 // r: 0..127
        int nglob = (r >> 6) * IDIM + n0 + (r & 63);
        bsrc[j] = w1t + ((size_t)e * 2 * IDIM + nglob) * DIM + ch * 4;
        bdst[j] = (unsigned)(G1_ASZ + r * PITCH + ch * 4) * 4;
    }

#pragma unroll
    for (int s = 0; s < 3; s++) {
        unsigned sb = sbase + s * (G1_STG * 4);
        int k0 = s * 32;
#pragma unroll
        for (int j = 0; j < 4; j++) cpa16(sb + adst[j], asrc[j] + k0);
#pragma unroll
        for (int j = 0; j < 4; j++) cpa16(sb + bdst[j], bsrc[j] + k0);
        asm volatile("cp.async.commit_group;" ::: "memory");
    }

    // ldmatrix per-lane offsets
    unsigned a_off = (unsigned)((warp_m * 64 + (lane & 15)) * PITCH + (lane >> 4) * 4) * 4;
    unsigned b_off = (unsigned)((warp_n * 16 + (lane & 7) + ((lane >> 4) & 1) * 8) * PITCH
                                + ((lane >> 3) & 1) * 4) * 4;

    float c1[4][2][4], c2[4][2][4];
#pragma unroll
    for (int mt = 0; mt < 4; mt++)
#pragma unroll
        for (int nt = 0; nt < 2; nt++)
#pragma unroll
            for (int j = 0; j < 4; j++) { c1[mt][nt][j] = 0.f; c2[mt][nt][j] = 0.f; }

    for (int it = 0; it < G1_NIT; it++) {
        asm volatile("cp.async.wait_group 2;" ::: "memory");
        __syncthreads();
        unsigned Ab  = sbase + (it & 3) * (G1_STG * 4);
        unsigned B1b = Ab + G1_ASZ * 4;
        unsigned B2b = B1b + G1_BSZ * 4;
#pragma unroll
        for (int kk = 0; kk < 32; kk += 8) {
            unsigned a[4][4], b1[4], b2[4];
#pragma unroll
            for (int mt = 0; mt < 4; mt++)
                ldsm4(a[mt], Ab + a_off + (unsigned)(mt * 16 * PITCH + kk) * 4);
            ldsm4(b1, B1b + b_off + (unsigned)kk * 4);
            ldsm4(b2, B2b + b_off + (unsigned)kk * 4);
#pragma unroll
            for (int g = 0; g < 2; g++)
#pragma unroll
                for (int mt = 0; mt < 4; mt++) {
                    mma_tf32(c1[mt][g], a[mt], b1[2 * g], b1[2 * g + 1]);
                    mma_tf32(c2[mt][g], a[mt], b2[2 * g], b2[2 * g + 1]);
                }
        }
        if (it + 3 < G1_NIT) {
            unsigned sb = sbase + ((it + 3) & 3) * (G1_STG * 4);
            int k0 = (it + 3) * 32;
#pragma unroll
            for (int j = 0; j < 4; j++) cpa16(sb + adst[j], asrc[j] + k0);
#pragma unroll
            for (int j = 0; j < 4; j++) cpa16(sb + bdst[j], bsrc[j] + k0);
        }
        asm volatile("cp.async.commit_group;" ::: "memory");
    }

    // epilogue: exact gelu(inp) * gate, stored tf32-rounded
#pragma unroll
    for (int mt = 0; mt < 4; mt++) {
#pragma unroll
        for (int half = 0; half < 2; half++) {
            int r = r0 + warp_m * 64 + mt * 16 + gid + half * 8;
            float* dst = g_hglu + ((size_t)(e * CAP + r)) * IDIM;
#pragma unroll
            for (int nt = 0; nt < 2; nt++) {
                float i0 = c1[mt][nt][2 * half + 0];
                float i1 = c1[mt][nt][2 * half + 1];
                float g0 = 0.5f * i0 * (1.0f + erff(i0 * 0.70710678118654752f));
                float g1 = 0.5f * i1 * (1.0f + erff(i1 * 0.70710678118654752f));
                float2 v;
                v.x = __uint_as_float(f2tf32(g0 * c2[mt][nt][2 * half + 0]));
                v.y = __uint_as_float(f2tf32(g1 * c2[mt][nt][2 * half + 1]));
                int col = n0 + warp_n * 16 + nt * 8 + 2 * tid4;
                *(float2*)(dst + col) = v;
            }
        }
    }
}

// ---------------------------------------------------------------------------
// GEMM2: block 128m x 256n, 256 thr, 8 warps (2x4), warp tile 64x64.
// A [128][32] pitch 36, B n-major [256][32] pitch 36. ldmatrix fragments.
// ---------------------------------------------------------------------------
#define G2_ASZ (128 * PITCH)             // 4608 u32
#define G2_BSZ (256 * PITCH)             // 9216 u32
#define G2_STG (G2_ASZ + G2_BSZ)         // 13824 u32
#define G2_NIT (IDIM / 32)               // 64
#define SMEM2_BYTES (4 * G2_STG * 4)     // 221184

__global__ __launch_bounds__(256, 1) void gemm2_kernel(const unsigned* __restrict__ w2t,
                                                       float* __restrict__ out) {
    extern __shared__ unsigned sm2[];

    int e   = blockIdx.z;
    int cnt = g_count[e];
    int r0  = blockIdx.y * 128;
    if (r0 >= cnt) return;
    int n0  = blockIdx.x * 256;
    int tid = threadIdx.x;
    int lane = tid & 31, warp = tid >> 5;
    int gid = lane >> 2, tid4 = lane & 3;
    int warp_m = warp >> 2;    // 0..1
    int warp_n = warp & 3;     // 0..3

    unsigned sbase = smem_u32(sm2);
    const unsigned* hbase = (const unsigned*)g_hglu + (size_t)e * CAP * IDIM;
    const unsigned* w2e   = w2t + (size_t)e * DIM * IDIM;

    const unsigned* asrc[4]; unsigned adst[4];
#pragma unroll
    for (int j = 0; j < 4; j++) {
        int c = tid + 256 * j;
        int row = c >> 3, ch = c & 7;
        asrc[j] = hbase + (size_t)(r0 + row) * IDIM + ch * 4;
        adst[j] = (unsigned)(row * PITCH + ch * 4) * 4;
    }
    const unsigned* bsrc[8]; unsigned bdst[8];
#pragma unroll
    for (int j = 0; j < 8; j++) {
        int c = tid + 256 * j;
        int r = c >> 3, ch = c & 7;                 // r: 0..255
        bsrc[j] = w2e + (size_t)(n0 + r) * IDIM + ch * 4;
        bdst[j] = (unsigned)(G2_ASZ + r * PITCH + ch * 4) * 4;
    }

#pragma unroll
    for (int s = 0; s < 3; s++) {
        unsigned sb = sbase + s * (G2_STG * 4);
        int k0 = s * 32;
#pragma unroll
        for (int j = 0; j < 4; j++) cpa16(sb + adst[j], asrc[j] + k0);
#pragma unroll
        for (int j = 0; j < 8; j++) cpa16(sb + bdst[j], bsrc[j] + k0);
        asm volatile("cp.async.commit_group;" ::: "memory");
    }

    unsigned a_off = (unsigned)((warp_m * 64 + (lane & 15)) * PITCH + (lane >> 4) * 4) * 4;
    unsigned b_off = (unsigned)((warp_n * 64 + (lane & 7) + ((lane >> 4) & 1) * 8) * PITCH
                                + ((lane >> 3) & 1) * 4) * 4;

    float c[4][8][4];
#pragma unroll
    for (int mt = 0; mt < 4; mt++)
#pragma unroll
        for (int nt = 0; nt < 8; nt++)
#pragma unroll
            for (int j = 0; j < 4; j++) c[mt][nt][j] = 0.f;

    for (int it = 0; it < G2_NIT; it++) {
        asm volatile("cp.async.wait_group 2;" ::: "memory");
        __syncthreads();
        unsigned Ab = sbase + (it & 3) * (G2_STG * 4);
        unsigned Bb = Ab + G2_ASZ * 4;
#pragma unroll
        for (int kk = 0; kk < 32; kk += 8) {
            unsigned a[4][4], bf[4][4];
#pragma unroll
            for (int mt = 0; mt < 4; mt++)
                ldsm4(a[mt], Ab + a_off + (unsigned)(mt * 16 * PITCH + kk) * 4);
#pragma unroll
            for (int p = 0; p < 4; p++)
                ldsm4(bf[p], Bb + b_off + (unsigned)(p * 16 * PITCH + kk) * 4);
#pragma unroll
            for (int nt = 0; nt < 8; nt++) {
                unsigned b0 = bf[nt >> 1][(nt & 1) * 2];
                unsigned b1 = bf[nt >> 1][(nt & 1) * 2 + 1];
#pragma unroll
                for (int mt = 0; mt < 4; mt++)
                    mma_tf32(c[mt][nt], a[mt], b0, b1);
            }
        }
        if (it + 3 < G2_NIT) {
            unsigned sb = sbase + ((it + 3) & 3) * (G2_STG * 4);
            int k0 = (it + 3) * 32;
#pragma unroll
            for (int j = 0; j < 4; j++) cpa16(sb + adst[j], asrc[j] + k0);
#pragma unroll
            for (int j = 0; j < 8; j++) cpa16(sb + bdst[j], bsrc[j] + k0);
        }
        asm volatile("cp.async.commit_group;" ::: "memory");
    }

    // gate-weighted scatter
#pragma unroll
    for (int mt = 0; mt < 4; mt++) {
#pragma unroll
        for (int half = 0; half < 2; half++) {
            int r = r0 + warp_m * 64 + mt * 16 + gid + half * 8;
            if (r < cnt) {
                int tok   = g_row2tok[e * CAP + r];
                float gte = g_rowgate[e * CAP + r];
                float* op = out + (size_t)tok * DIM + n0 + warp_n * 64 + 2 * tid4;
#pragma unroll
                for (int nt = 0; nt < 8; nt++) {
                    float v0 = gte * c[mt][nt][2 * half + 0];
                    float v1 = gte * c[mt][nt][2 * half + 1];
                    asm volatile("red.global.add.v2.f32 [%0], {%1, %2};"
                                 :: "l"(op + nt * 8), "f"(v0), "f"(v1) : "memory");
                }
            }
        }
    }
}

// ---------------------------------------------------------------------------
extern "C" void kernel_launch(void* const* d_in, const int* in_sizes, int n_in,
                              void* d_out, int out_size) {
    const float* x  = (const float*)d_in[0];
    const float* Wg = (const float*)d_in[1];
    const float* W1 = (const float*)d_in[2];
    const float* W2 = (const float*)d_in[3];
    float* out = (float*)d_out;

    cudaFuncSetAttribute(gemm1_kernel, cudaFuncAttributeMaxDynamicSharedMemorySize, SMEM1_BYTES);
    cudaFuncSetAttribute(gemm2_kernel, cudaFuncAttributeMaxDynamicSharedMemorySize, SMEM2_BYTES);

    unsigned *xc, *w1t, *w2t;
    cudaGetSymbolAddress((void**)&xc,  g_xc);
    cudaGetSymbolAddress((void**)&w1t, g_w1t);
    cudaGetSymbolAddress((void**)&w2t, g_w2t);

    cudaMemsetAsync(out, 0, (size_t)NTOK * DIM * sizeof(float));

    cvt_kernel<<<(NTOK * DIM / 4 + 255) / 256, 256>>>(x, xc, NTOK * DIM / 4);
    {
        dim3 b(32, 8);
        dim3 gw1(2 * IDIM / 32, DIM / 32, NEXP);
        cvtT_kernel<<<gw1, b>>>(W1, w1t, DIM, 2 * IDIM);
        dim3 gw2(DIM / 32, IDIM / 32, NEXP);
        cvtT_kernel<<<gw2, b>>>(W2, w2t, IDIM, DIM);
    }

    router_kernel<<<NTOK / 8, 256>>>(x, Wg);
    scan_kernel<<<1, 256>>>();

    dim3 g1(IDIM / 64, CAP / 128, NEXP);    // (32, 10, 8)
    gemm1_kernel<<<g1, 256, SMEM1_BYTES>>>(xc, w1t);

    dim3 g2(DIM / 256, CAP / 128, NEXP);    // (4, 10, 8)
    gemm2_kernel<<<g2, 256, SMEM2_BYTES>>>(w2t, out);
}

// round 12
// speedup vs baseline: 3.6991x; 1.1169x over previous
#include <cuda_runtime.h>
#include <math.h>

// Problem constants
#define NTOK 4096
#define DIM  1024
#define NEXP 8
#define IDIM 2048
#define CAP  1280
#define NSLOT (NTOK*2)

// Scratch (static; no cudaMalloc allowed)
__device__ float    g_hglu[(size_t)NEXP * CAP * IDIM];        // 84 MB (tf32-rounded f32)
__device__ unsigned g_xc [(size_t)NTOK * DIM];                // x tf32, [tok][k]
__device__ unsigned g_w1t[(size_t)NEXP * 2 * IDIM * DIM];     // W1^T tf32, [e][n][k]
__device__ unsigned g_w2t[(size_t)NEXP * DIM * IDIM];         // W2^T tf32, [e][n][k]
__device__ int   g_row2tok[NEXP * CAP];
__device__ float g_rowgate[NEXP * CAP];
__device__ int   g_count[NEXP];
__device__ int   g_slot_e[NSLOT];
__device__ float g_slot_g[NSLOT];

__device__ __forceinline__ unsigned f2tf32(float f) {
    unsigned r;
    asm("cvt.rna.tf32.f32 %0, %1;" : "=r"(r) : "f"(f));
    return r;
}
__device__ __forceinline__ void mma_tf32(float* c, const unsigned* a, unsigned b0, unsigned b1) {
    asm volatile(
        "mma.sync.aligned.m16n8k8.row.col.f32.tf32.tf32.f32 "
        "{%0,%1,%2,%3}, {%4,%5,%6,%7}, {%8,%9}, {%0,%1,%2,%3};\n"
        : "+f"(c[0]), "+f"(c[1]), "+f"(c[2]), "+f"(c[3])
        : "r"(a[0]), "r"(a[1]), "r"(a[2]), "r"(a[3]), "r"(b0), "r"(b1));
}
__device__ __forceinline__ void cpa16(unsigned smem_addr, const void* gptr) {
    asm volatile("cp.async.cg.shared.global [%0], [%1], 16;"
                 :: "r"(smem_addr), "l"(gptr) : "memory");
}
__device__ __forceinline__ void ldsm4(unsigned* r, unsigned addr) {
    asm volatile("ldmatrix.sync.aligned.m8n8.x4.shared.b16 {%0,%1,%2,%3}, [%4];"
                 : "=r"(r[0]), "=r"(r[1]), "=r"(r[2]), "=r"(r[3]) : "r"(addr));
}
__device__ __forceinline__ unsigned smem_u32(const void* p) {
    unsigned a;
    asm("{ .reg .u64 t; cvta.to.shared.u64 t, %1; cvt.u32.u64 %0, t; }" : "=r"(a) : "l"(p));
    return a;
}

// ---------------------------------------------------------------------------
// Pre-convert: x -> tf32; W -> transpose [e][n][k] + tf32
// ---------------------------------------------------------------------------
__global__ void cvt_kernel(const float* __restrict__ src, unsigned* __restrict__ dst, int n4) {
    int i = blockIdx.x * blockDim.x + threadIdx.x;
    if (i < n4) {
        float4 v = ((const float4*)src)[i];
        uint4 o;
        o.x = f2tf32(v.x); o.y = f2tf32(v.y); o.z = f2tf32(v.z); o.w = f2tf32(v.w);
        ((uint4*)dst)[i] = o;
    }
}
__global__ void cvtT_kernel(const float* __restrict__ src, unsigned* __restrict__ dst,
                            int R, int C) {
    __shared__ float t[32][33];
    int e = blockIdx.z;
    const float* s = src + (size_t)e * R * C;
    unsigned* d = dst + (size_t)e * R * C;
    int c0 = blockIdx.x * 32, r0 = blockIdx.y * 32;
#pragma unroll
    for (int j = 0; j < 32; j += 8)
        t[threadIdx.y + j][threadIdx.x] = s[(size_t)(r0 + threadIdx.y + j) * C + c0 + threadIdx.x];
    __syncthreads();
#pragma unroll
    for (int j = 0; j < 32; j += 8)
        d[(size_t)(c0 + threadIdx.y + j) * R + r0 + threadIdx.x] = f2tf32(t[threadIdx.x][threadIdx.y + j]);
}

// ---------------------------------------------------------------------------
// Router
// ---------------------------------------------------------------------------
__global__ void router_kernel(const float* __restrict__ x,
                              const float* __restrict__ Wg) {
    int warp = (blockIdx.x * blockDim.x + threadIdx.x) >> 5;
    int lane = threadIdx.x & 31;
    if (warp >= NTOK) return;
    const float* xr = x + (size_t)warp * DIM;
    float acc[NEXP];
#pragma unroll
    for (int e = 0; e < NEXP; e++) acc[e] = 0.f;
    for (int i = lane; i < DIM; i += 32) {
        float xv = __ldg(xr + i);
#pragma unroll
        for (int e = 0; e < NEXP; e++) acc[e] += xv * __ldg(Wg + e * DIM + i);
    }
#pragma unroll
    for (int e = 0; e < NEXP; e++) {
#pragma unroll
        for (int off = 16; off > 0; off >>= 1)
            acc[e] += __shfl_xor_sync(0xffffffffu, acc[e], off);
    }
    if (lane == 0) {
        int i0 = 0; float v0 = acc[0];
#pragma unroll
        for (int e = 1; e < NEXP; e++) if (acc[e] > v0) { v0 = acc[e]; i0 = e; }
        int i1 = -1; float v1 = -1e30f;
#pragma unroll
        for (int e = 0; e < NEXP; e++)
            if (e != i0 && acc[e] > v1) { v1 = acc[e]; i1 = e; }
        float e0 = expf(v0 - v0), e1 = expf(v1 - v0);
        float inv = 1.0f / (e0 + e1);
        g_slot_e[2 * warp + 0] = i0; g_slot_g[2 * warp + 0] = e0 * inv;
        g_slot_e[2 * warp + 1] = i1; g_slot_g[2 * warp + 1] = e1 * inv;
    }
}

// ---------------------------------------------------------------------------
// Capacity scan
// ---------------------------------------------------------------------------
__global__ void scan_kernel() {
    __shared__ int smc[256][NEXP];
    int tid = threadIdx.x;
    for (int i = tid; i < NEXP * CAP; i += 256) {
        g_row2tok[i] = 0;
        g_rowgate[i] = 0.f;
    }
    const int PER = NSLOT / 256;
    int s0 = tid * PER;
    int le[PER];
    int c[NEXP];
#pragma unroll
    for (int e = 0; e < NEXP; e++) c[e] = 0;
#pragma unroll
    for (int j = 0; j < PER; j++) {
        int e = g_slot_e[s0 + j];
        le[j] = e;
        c[e]++;
    }
#pragma unroll
    for (int e = 0; e < NEXP; e++) smc[tid][e] = c[e];
    __syncthreads();
    if (tid < NEXP) {
        int run = 0;
        for (int t = 0; t < 256; t++) {
            int v = smc[t][tid];
            smc[t][tid] = run;
            run += v;
        }
        g_count[tid] = run < CAP ? run : CAP;
    }
    __syncthreads();
    int off[NEXP];
#pragma unroll
    for (int e = 0; e < NEXP; e++) off[e] = smc[tid][e];
#pragma unroll
    for (int j = 0; j < PER; j++) {
        int e = le[j];
        int p = off[e]++;
        if (p < CAP) {
            int slot = s0 + j;
            g_row2tok[e * CAP + p] = slot >> 1;
            g_rowgate[e * CAP + p] = g_slot_g[slot];
        }
    }
}

// ---------------------------------------------------------------------------
// GEMM1: block 128m x 64 pair-cols, 256 thr, 8 warps (2x4), warp 64m x 16pair.
// 3-stage cp.async, 2 CTAs/SM. ldmatrix fragments, pitch 36.
// ---------------------------------------------------------------------------
#define PITCH 36
#define G1_ASZ (128 * PITCH)             // 4608 u32
#define G1_BSZ (64 * PITCH)              // 2304 u32
#define G1_STG (G1_ASZ + 2 * G1_BSZ)     // 9216 u32
#define G1_NIT (DIM / 32)                // 32
#define SMEM1_BYTES ((3 * G1_STG + 128) * 4)   // 111104

__global__ __launch_bounds__(256, 2) void gemm1_kernel(const unsigned* __restrict__ xc,
                                                       const unsigned* __restrict__ w1t) {
    extern __shared__ unsigned sm1[];
    int* stok = (int*)(sm1 + 3 * G1_STG);

    int e   = blockIdx.z;
    int cnt = g_count[e];
    int r0  = blockIdx.y * 128;
    if (r0 >= cnt) return;
    int n0  = blockIdx.x * 64;
    int tid = threadIdx.x;
    int lane = tid & 31, warp = tid >> 5;
    int gid = lane >> 2, tid4 = lane & 3;
    int warp_m = warp >> 2;    // 0..1
    int warp_n = warp & 3;     // 0..3

    if (tid < 128) stok[tid] = g_row2tok[e * CAP + r0 + tid];
    __syncthreads();

    unsigned sbase = smem_u32(sm1);

    const unsigned* asrc[4]; unsigned adst[4];
#pragma unroll
    for (int j = 0; j < 4; j++) {
        int c = tid + 256 * j;
        int row = c >> 3, ch = c & 7;
        asrc[j] = xc + (size_t)stok[row] * DIM + ch * 4;
        adst[j] = (unsigned)(row * PITCH + ch * 4) * 4;
    }
    const unsigned* bsrc[4]; unsigned bdst[4];
#pragma unroll
    for (int j = 0; j < 4; j++) {
        int c = tid + 256 * j;
        int r = c >> 3, ch = c & 7;                 // r: 0..127
        int nglob = (r >> 6) * IDIM + n0 + (r & 63);
        bsrc[j] = w1t + ((size_t)e * 2 * IDIM + nglob) * DIM + ch * 4;
        bdst[j] = (unsigned)(G1_ASZ + r * PITCH + ch * 4) * 4;
    }

#pragma unroll
    for (int s = 0; s < 2; s++) {
        unsigned sb = sbase + s * (G1_STG * 4);
        int k0 = s * 32;
#pragma unroll
        for (int j = 0; j < 4; j++) cpa16(sb + adst[j], asrc[j] + k0);
#pragma unroll
        for (int j = 0; j < 4; j++) cpa16(sb + bdst[j], bsrc[j] + k0);
        asm volatile("cp.async.commit_group;" ::: "memory");
    }

    unsigned a_off = (unsigned)((warp_m * 64 + (lane & 15)) * PITCH + (lane >> 4) * 4) * 4;
    unsigned b_off = (unsigned)((warp_n * 16 + (lane & 7) + ((lane >> 4) & 1) * 8) * PITCH
                                + ((lane >> 3) & 1) * 4) * 4;

    float c1[4][2][4], c2[4][2][4];
#pragma unroll
    for (int mt = 0; mt < 4; mt++)
#pragma unroll
        for (int nt = 0; nt < 2; nt++)
#pragma unroll
            for (int j = 0; j < 4; j++) { c1[mt][nt][j] = 0.f; c2[mt][nt][j] = 0.f; }

    int st_c = 0, st_p = 2;
    for (int it = 0; it < G1_NIT; it++) {
        asm volatile("cp.async.wait_group 1;" ::: "memory");
        __syncthreads();
        unsigned Ab  = sbase + st_c * (G1_STG * 4);
        unsigned B1b = Ab + G1_ASZ * 4;
        unsigned B2b = B1b + G1_BSZ * 4;
#pragma unroll
        for (int kk = 0; kk < 32; kk += 8) {
            unsigned a[4][4], b1[4], b2[4];
#pragma unroll
            for (int mt = 0; mt < 4; mt++)
                ldsm4(a[mt], Ab + a_off + (unsigned)(mt * 16 * PITCH + kk) * 4);
            ldsm4(b1, B1b + b_off + (unsigned)kk * 4);
            ldsm4(b2, B2b + b_off + (unsigned)kk * 4);
#pragma unroll
            for (int g = 0; g < 2; g++)
#pragma unroll
                for (int mt = 0; mt < 4; mt++) {
                    mma_tf32(c1[mt][g], a[mt], b1[2 * g], b1[2 * g + 1]);
                    mma_tf32(c2[mt][g], a[mt], b2[2 * g], b2[2 * g + 1]);
                }
        }
        if (it + 2 < G1_NIT) {
            unsigned sb = sbase + st_p * (G1_STG * 4);
            int k0 = (it + 2) * 32;
#pragma unroll
            for (int j = 0; j < 4; j++) cpa16(sb + adst[j], asrc[j] + k0);
#pragma unroll
            for (int j = 0; j < 4; j++) cpa16(sb + bdst[j], bsrc[j] + k0);
        }
        asm volatile("cp.async.commit_group;" ::: "memory");
        st_c = (st_c == 2) ? 0 : st_c + 1;
        st_p = (st_p == 2) ? 0 : st_p + 1;
    }

    // epilogue: exact gelu(inp) * gate, stored tf32-rounded
#pragma unroll
    for (int mt = 0; mt < 4; mt++) {
#pragma unroll
        for (int half = 0; half < 2; half++) {
            int r = r0 + warp_m * 64 + mt * 16 + gid + half * 8;
            float* dst = g_hglu + ((size_t)(e * CAP + r)) * IDIM;
#pragma unroll
            for (int nt = 0; nt < 2; nt++) {
                float i0 = c1[mt][nt][2 * half + 0];
                float i1 = c1[mt][nt][2 * half + 1];
                float g0 = 0.5f * i0 * (1.0f + erff(i0 * 0.70710678118654752f));
                float g1 = 0.5f * i1 * (1.0f + erff(i1 * 0.70710678118654752f));
                float2 v;
                v.x = __uint_as_float(f2tf32(g0 * c2[mt][nt][2 * half + 0]));
                v.y = __uint_as_float(f2tf32(g1 * c2[mt][nt][2 * half + 1]));
                int col = n0 + warp_n * 16 + nt * 8 + 2 * tid4;
                *(float2*)(dst + col) = v;
            }
        }
    }
}

// ---------------------------------------------------------------------------
// GEMM2: block 128m x 128n, 256 thr, 8 warps (2x4), warp 64m x 32n.
// 3-stage cp.async, 2 CTAs/SM. ldmatrix fragments, pitch 36.
// ---------------------------------------------------------------------------
#define G2_ASZ (128 * PITCH)             // 4608 u32
#define G2_BSZ (128 * PITCH)             // 4608 u32
#define G2_STG (G2_ASZ + G2_BSZ)         // 9216 u32
#define G2_NIT (IDIM / 32)               // 64
#define SMEM2_BYTES (3 * G2_STG * 4)     // 110592

__global__ __launch_bounds__(256, 2) void gemm2_kernel(const unsigned* __restrict__ w2t,
                                                       float* __restrict__ out) {
    extern __shared__ unsigned sm2[];

    int e   = blockIdx.z;
    int cnt = g_count[e];
    int r0  = blockIdx.y * 128;
    if (r0 >= cnt) return;
    int n0  = blockIdx.x * 128;
    int tid = threadIdx.x;
    int lane = tid & 31, warp = tid >> 5;
    int gid = lane >> 2, tid4 = lane & 3;
    int warp_m = warp >> 2;    // 0..1
    int warp_n = warp & 3;     // 0..3

    unsigned sbase = smem_u32(sm2);
    const unsigned* hbase = (const unsigned*)g_hglu + (size_t)e * CAP * IDIM;
    const unsigned* w2e   = w2t + (size_t)e * DIM * IDIM;

    const unsigned* asrc[4]; unsigned adst[4];
#pragma unroll
    for (int j = 0; j < 4; j++) {
        int c = tid + 256 * j;
        int row = c >> 3, ch = c & 7;
        asrc[j] = hbase + (size_t)(r0 + row) * IDIM + ch * 4;
        adst[j] = (unsigned)(row * PITCH + ch * 4) * 4;
    }
    const unsigned* bsrc[4]; unsigned bdst[4];
#pragma unroll
    for (int j = 0; j < 4; j++) {
        int c = tid + 256 * j;
        int r = c >> 3, ch = c & 7;                 // r: 0..127
        bsrc[j] = w2e + (size_t)(n0 + r) * IDIM + ch * 4;
        bdst[j] = (unsigned)(G2_ASZ + r * PITCH + ch * 4) * 4;
    }

#pragma unroll
    for (int s = 0; s < 2; s++) {
        unsigned sb = sbase + s * (G2_STG * 4);
        int k0 = s * 32;
#pragma unroll
        for (int j = 0; j < 4; j++) cpa16(sb + adst[j], asrc[j] + k0);
#pragma unroll
        for (int j = 0; j < 4; j++) cpa16(sb + bdst[j], bsrc[j] + k0);
        asm volatile("cp.async.commit_group;" ::: "memory");
    }

    unsigned a_off = (unsigned)((warp_m * 64 + (lane & 15)) * PITCH + (lane >> 4) * 4) * 4;
    unsigned b_off = (unsigned)((warp_n * 32 + (lane & 7) + ((lane >> 4) & 1) * 8) * PITCH
                                + ((lane >> 3) & 1) * 4) * 4;

    float c[4][4][4];
#pragma unroll
    for (int mt = 0; mt < 4; mt++)
#pragma unroll
        for (int nt = 0; nt < 4; nt++)
#pragma unroll
            for (int j = 0; j < 4; j++) c[mt][nt][j] = 0.f;

    int st_c = 0, st_p = 2;
    for (int it = 0; it < G2_NIT; it++) {
        asm volatile("cp.async.wait_group 1;" ::: "memory");
        __syncthreads();
        unsigned Ab = sbase + st_c * (G2_STG * 4);
        unsigned Bb = Ab + G2_ASZ * 4;
#pragma unroll
        for (int kk = 0; kk < 32; kk += 8) {
            unsigned a[4][4], bf[2][4];
#pragma unroll
            for (int mt = 0; mt < 4; mt++)
                ldsm4(a[mt], Ab + a_off + (unsigned)(mt * 16 * PITCH + kk) * 4);
#pragma unroll
            for (int p = 0; p < 2; p++)
                ldsm4(bf[p], Bb + b_off + (unsigned)(p * 16 * PITCH + kk) * 4);
#pragma unroll
            for (int nt = 0; nt < 4; nt++) {
                unsigned b0 = bf[nt >> 1][(nt & 1) * 2];
                unsigned b1 = bf[nt >> 1][(nt & 1) * 2 + 1];
#pragma unroll
                for (int mt = 0; mt < 4; mt++)
                    mma_tf32(c[mt][nt], a[mt], b0, b1);
            }
        }
        if (it + 2 < G2_NIT) {
            unsigned sb = sbase + st_p * (G2_STG * 4);
            int k0 = (it + 2) * 32;
#pragma unroll
            for (int j = 0; j < 4; j++) cpa16(sb + adst[j], asrc[j] + k0);
#pragma unroll
            for (int j = 0; j < 4; j++) cpa16(sb + bdst[j], bsrc[j] + k0);
        }
        asm volatile("cp.async.commit_group;" ::: "memory");
        st_c = (st_c == 2) ? 0 : st_c + 1;
        st_p = (st_p == 2) ? 0 : st_p + 1;
    }

    // gate-weighted scatter
#pragma unroll
    for (int mt = 0; mt < 4; mt++) {
#pragma unroll
        for (int half = 0; half < 2; half++) {
            int r = r0 + warp_m * 64 + mt * 16 + gid + half * 8;
            if (r < cnt) {
                int tok   = g_row2tok[e * CAP + r];
                float gte = g_rowgate[e * CAP + r];
                float* op = out + (size_t)tok * DIM + n0 + warp_n * 32 + 2 * tid4;
#pragma unroll
                for (int nt = 0; nt < 4; nt++) {
                    float v0 = gte * c[mt][nt][2 * half + 0];
                    float v1 = gte * c[mt][nt][2 * half + 1];
                    asm volatile("red.global.add.v2.f32 [%0], {%1, %2};"
                                 :: "l"(op + nt * 8), "f"(v0), "f"(v1) : "memory");
                }
            }
        }
    }
}

// ---------------------------------------------------------------------------
extern "C" void kernel_launch(void* const* d_in, const int* in_sizes, int n_in,
                              void* d_out, int out_size) {
    const float* x  = (const float*)d_in[0];
    const float* Wg = (const float*)d_in[1];
    const float* W1 = (const float*)d_in[2];
    const float* W2 = (const float*)d_in[3];
    float* out = (float*)d_out;

    cudaFuncSetAttribute(gemm1_kernel, cudaFuncAttributeMaxDynamicSharedMemorySize, SMEM1_BYTES);
    cudaFuncSetAttribute(gemm2_kernel, cudaFuncAttributeMaxDynamicSharedMemorySize, SMEM2_BYTES);

    unsigned *xc, *w1t, *w2t;
    cudaGetSymbolAddress((void**)&xc,  g_xc);
    cudaGetSymbolAddress((void**)&w1t, g_w1t);
    cudaGetSymbolAddress((void**)&w2t, g_w2t);

    cudaMemsetAsync(out, 0, (size_t)NTOK * DIM * sizeof(float));

    cvt_kernel<<<(NTOK * DIM / 4 + 255) / 256, 256>>>(x, xc, NTOK * DIM / 4);
    {
        dim3 b(32, 8);
        dim3 gw1(2 * IDIM / 32, DIM / 32, NEXP);
        cvtT_kernel<<<gw1, b>>>(W1, w1t, DIM, 2 * IDIM);
        dim3 gw2(DIM / 32, IDIM / 32, NEXP);
        cvtT_kernel<<<gw2, b>>>(W2, w2t, IDIM, DIM);
    }

    router_kernel<<<NTOK / 8, 256>>>(x, Wg);
    scan_kernel<<<1, 256>>>();

    dim3 g1(IDIM / 64, CAP / 128, NEXP);    // (32, 10, 8)
    gemm1_kernel<<<g1, 256, SMEM1_BYTES>>>(xc, w1t);

    dim3 g2(DIM / 128, CAP / 128, NEXP);    // (8, 10, 8)
    gemm2_kernel<<<g2, 256, SMEM2_BYTES>>>(w2t, out);
}

// round 16
// speedup vs baseline: 3.7648x; 1.0178x over previous
#include <cuda_runtime.h>
#include <math.h>

// Problem constants
#define NTOK 4096
#define DIM  1024
#define NEXP 8
#define IDIM 2048
#define CAP  1280
#define NSLOT (NTOK*2)

// Scratch (static; no cudaMalloc allowed)
__device__ float    g_hglu[(size_t)NEXP * CAP * IDIM];        // 84 MB (tf32-rounded f32)
__device__ unsigned g_xc [(size_t)NTOK * DIM];                // x tf32, [tok][k]
__device__ unsigned g_w1t[(size_t)NEXP * 2 * IDIM * DIM];     // W1^T tf32, [e][n][k]
__device__ unsigned g_w2t[(size_t)NEXP * DIM * IDIM];         // W2^T tf32, [e][n][k]
__device__ int   g_row2tok[NEXP * CAP];
__device__ float g_rowgate[NEXP * CAP];
__device__ int   g_count[NEXP];
__device__ int   g_slot_e[NSLOT];
__device__ float g_slot_g[NSLOT];

__device__ __forceinline__ unsigned f2tf32(float f) {
    unsigned r;
    asm("cvt.rna.tf32.f32 %0, %1;" : "=r"(r) : "f"(f));
    return r;
}
__device__ __forceinline__ void mma_tf32(float* c, const unsigned* a, unsigned b0, unsigned b1) {
    asm volatile(
        "mma.sync.aligned.m16n8k8.row.col.f32.tf32.tf32.f32 "
        "{%0,%1,%2,%3}, {%4,%5,%6,%7}, {%8,%9}, {%0,%1,%2,%3};\n"
        : "+f"(c[0]), "+f"(c[1]), "+f"(c[2]), "+f"(c[3])
        : "r"(a[0]), "r"(a[1]), "r"(a[2]), "r"(a[3]), "r"(b0), "r"(b1));
}
__device__ __forceinline__ void cpa16(unsigned smem_addr, const void* gptr) {
    asm volatile("cp.async.cg.shared.global [%0], [%1], 16;"
                 :: "r"(smem_addr), "l"(gptr) : "memory");
}
__device__ __forceinline__ void ldsm4(unsigned* r, unsigned addr) {
    asm volatile("ldmatrix.sync.aligned.m8n8.x4.shared.b16 {%0,%1,%2,%3}, [%4];"
                 : "=r"(r[0]), "=r"(r[1]), "=r"(r[2]), "=r"(r[3]) : "r"(addr));
}
__device__ __forceinline__ unsigned smem_u32(const void* p) {
    unsigned a;
    asm("{ .reg .u64 t; cvta.to.shared.u64 t, %1; cvt.u32.u64 %0, t; }" : "=r"(a) : "l"(p));
    return a;
}

// ---------------------------------------------------------------------------
// Pre-kernel: blocks [0,512) = router (also emits x as tf32 into g_xc).
//             blocks [512, 512+32768) = W1 transpose+convert -> g_w1t.
// One launch; both parts run concurrently on one stream.
// ---------------------------------------------------------------------------
#define PRE_ROUTER_BLOCKS 512
#define W1T_TILES (NEXP * (DIM / 32) * (2 * IDIM / 32))   // 32768

__global__ __launch_bounds__(256) void pre_kernel(const float* __restrict__ x,
                                                  const float* __restrict__ Wg,
                                                  const float* __restrict__ W1) {
    __shared__ float t[32][33];
    int b = blockIdx.x;
    int tid = threadIdx.x;

    if (b < PRE_ROUTER_BLOCKS) {
        // ------- router -------
        int warp = b * 8 + (tid >> 5);
        int lane = tid & 31;
        const float* xr = x + (size_t)warp * DIM;
        unsigned* xco = g_xc + (size_t)warp * DIM;
        float acc[NEXP];
#pragma unroll
        for (int e = 0; e < NEXP; e++) acc[e] = 0.f;
        for (int i = lane; i < DIM; i += 32) {
            float xv = __ldg(xr + i);
            xco[i] = f2tf32(xv);
#pragma unroll
            for (int e = 0; e < NEXP; e++) acc[e] += xv * __ldg(Wg + e * DIM + i);
        }
#pragma unroll
        for (int e = 0; e < NEXP; e++) {
#pragma unroll
            for (int off = 16; off > 0; off >>= 1)
                acc[e] += __shfl_xor_sync(0xffffffffu, acc[e], off);
        }
        if (lane == 0) {
            int i0 = 0; float v0 = acc[0];
#pragma unroll
            for (int e = 1; e < NEXP; e++) if (acc[e] > v0) { v0 = acc[e]; i0 = e; }
            int i1 = -1; float v1 = -1e30f;
#pragma unroll
            for (int e = 0; e < NEXP; e++)
                if (e != i0 && acc[e] > v1) { v1 = acc[e]; i1 = e; }
            float e0 = expf(v0 - v0), e1 = expf(v1 - v0);
            float inv = 1.0f / (e0 + e1);
            g_slot_e[2 * warp + 0] = i0; g_slot_g[2 * warp + 0] = e0 * inv;
            g_slot_e[2 * warp + 1] = i1; g_slot_g[2 * warp + 1] = e1 * inv;
        }
    } else {
        // ------- W1 transpose: src[e][DIM][2*IDIM] -> dst[e][2*IDIM][DIM] -------
        int bp = b - PRE_ROUTER_BLOCKS;               // 0..32767
        int e   = bp >> 12;                           // 4096 tiles/expert
        int rem = bp & 4095;
        int rt  = rem >> 7;                           // 0..31  (rows of src)
        int ct  = rem & 127;                          // 0..127 (cols of src)
        int r0 = rt * 32, c0 = ct * 32;
        const int R = DIM, C = 2 * IDIM;
        const float* s = W1 + (size_t)e * R * C;
        unsigned* d = g_w1t + (size_t)e * R * C;
        int tx = tid & 31, ty = tid >> 5;             // 32 x 8
#pragma unroll
        for (int j = 0; j < 32; j += 8)
            t[ty + j][tx] = s[(size_t)(r0 + ty + j) * C + c0 + tx];
        __syncthreads();
#pragma unroll
        for (int j = 0; j < 32; j += 8)
            d[(size_t)(c0 + ty + j) * R + r0 + tx] = f2tf32(t[tx][ty + j]);
    }
}

// ---------------------------------------------------------------------------
// Capacity scan
// ---------------------------------------------------------------------------
__global__ void scan_kernel() {
    __shared__ int smc[256][NEXP];
    int tid = threadIdx.x;
    for (int i = tid; i < NEXP * CAP; i += 256) {
        g_row2tok[i] = 0;
        g_rowgate[i] = 0.f;
    }
    const int PER = NSLOT / 256;
    int s0 = tid * PER;
    int le[PER];
    int c[NEXP];
#pragma unroll
    for (int e = 0; e < NEXP; e++) c[e] = 0;
#pragma unroll
    for (int j = 0; j < PER; j++) {
        int e = g_slot_e[s0 + j];
        le[j] = e;
        c[e]++;
    }
#pragma unroll
    for (int e = 0; e < NEXP; e++) smc[tid][e] = c[e];
    __syncthreads();
    if (tid < NEXP) {
        int run = 0;
        for (int t = 0; t < 256; t++) {
            int v = smc[t][tid];
            smc[t][tid] = run;
            run += v;
        }
        g_count[tid] = run < CAP ? run : CAP;
    }
    __syncthreads();
    int off[NEXP];
#pragma unroll
    for (int e = 0; e < NEXP; e++) off[e] = smc[tid][e];
#pragma unroll
    for (int j = 0; j < PER; j++) {
        int e = le[j];
        int p = off[e]++;
        if (p < CAP) {
            int slot = s0 + j;
            g_row2tok[e * CAP + p] = slot >> 1;
            g_rowgate[e * CAP + p] = g_slot_g[slot];
        }
    }
}

// ---------------------------------------------------------------------------
// GEMM1: block 128m x 64 pair-cols, 256 thr, 8 warps (2x4), warp 64m x 16pair.
// 3-stage cp.async, 2 CTAs/SM. ldmatrix fragments, pitch 36.
// Extra blockIdx.z slices (z >= 8) perform the W2 transpose (g_w2t), which
// only gemm2 needs — overlapping it with gemm1 compute in one launch.
// ---------------------------------------------------------------------------
#define PITCH 36
#define G1_ASZ (128 * PITCH)             // 4608 u32
#define G1_BSZ (64 * PITCH)              // 2304 u32
#define G1_STG (G1_ASZ + 2 * G1_BSZ)     // 9216 u32
#define G1_NIT (DIM / 32)                // 32
#define SMEM1_BYTES ((3 * G1_STG + 128) * 4)   // 111104

#define W2T_TILES (NEXP * (IDIM / 32) * (DIM / 32))   // 16384
#define G1_XB 32
#define G1_YB (CAP / 128)                              // 10
#define W2T_ZSLICES ((W2T_TILES + G1_XB * G1_YB - 1) / (G1_XB * G1_YB))  // 52

__global__ __launch_bounds__(256, 2) void gemm1_kernel(const unsigned* __restrict__ xc,
                                                       const unsigned* __restrict__ w1t,
                                                       const float* __restrict__ W2) {
    extern __shared__ unsigned sm1[];

    if (blockIdx.z >= NEXP) {
        // ------- W2 transpose: src[e][IDIM][DIM] -> dst[e][DIM][IDIM] -------
        int tile = (blockIdx.z - NEXP) * (G1_XB * G1_YB) + blockIdx.y * G1_XB + blockIdx.x;
        if (tile >= W2T_TILES) return;
        float* t = (float*)sm1;                       // [32][33]
        int e   = tile >> 11;                         // 2048 tiles/expert
        int rem = tile & 2047;
        int rt  = rem >> 5;                           // 0..63 (rows of src, R=IDIM)
        int ct  = rem & 31;                           // 0..31 (cols of src, C=DIM)
        int r0 = rt * 32, c0 = ct * 32;
        const int R = IDIM, C = DIM;
        const float* s = W2 + (size_t)e * R * C;
        unsigned* d = g_w2t + (size_t)e * R * C;
        int tid = threadIdx.x;
        int tx = tid & 31, ty = tid >> 5;
#pragma unroll
        for (int j = 0; j < 32; j += 8)
            t[(ty + j) * 33 + tx] = s[(size_t)(r0 + ty + j) * C + c0 + tx];
        __syncthreads();
#pragma unroll
        for (int j = 0; j < 32; j += 8)
            d[(size_t)(c0 + ty + j) * R + r0 + tx] = f2tf32(t[tx * 33 + ty + j]);
        return;
    }

    int* stok = (int*)(sm1 + 3 * G1_STG);

    int e   = blockIdx.z;
    int cnt = g_count[e];
    int r0  = blockIdx.y * 128;
    if (r0 >= cnt) return;
    int n0  = blockIdx.x * 64;
    int tid = threadIdx.x;
    int lane = tid & 31, warp = tid >> 5;
    int gid = lane >> 2, tid4 = lane & 3;
    int warp_m = warp >> 2;    // 0..1
    int warp_n = warp & 3;     // 0..3

    if (tid < 128) stok[tid] = g_row2tok[e * CAP + r0 + tid];
    __syncthreads();

    unsigned sbase = smem_u32(sm1);

    const unsigned* asrc[4]; unsigned adst[4];
#pragma unroll
    for (int j = 0; j < 4; j++) {
        int c = tid + 256 * j;
        int row = c >> 3, ch = c & 7;
        asrc[j] = xc + (size_t)stok[row] * DIM + ch * 4;
        adst[j] = (unsigned)(row * PITCH + ch * 4) * 4;
    }
    const unsigned* bsrc[4]; unsigned bdst[4];
#pragma unroll
    for (int j = 0; j < 4; j++) {
        int c = tid + 256 * j;
        int r = c >> 3, ch = c & 7;                 // r: 0..127
        int nglob = (r >> 6) * IDIM + n0 + (r & 63);
        bsrc[j] = w1t + ((size_t)e * 2 * IDIM + nglob) * DIM + ch * 4;
        bdst[j] = (unsigned)(G1_ASZ + r * PITCH + ch * 4) * 4;
    }

#pragma unroll
    for (int s = 0; s < 2; s++) {
        unsigned sb = sbase + s * (G1_STG * 4);
        int k0 = s * 32;
#pragma unroll
        for (int j = 0; j < 4; j++) cpa16(sb + adst[j], asrc[j] + k0);
#pragma unroll
        for (int j = 0; j < 4; j++) cpa16(sb + bdst[j], bsrc[j] + k0);
        asm volatile("cp.async.commit_group;" ::: "memory");
    }

    unsigned a_off = (unsigned)((warp_m * 64 + (lane & 15)) * PITCH + (lane >> 4) * 4) * 4;
    unsigned b_off = (unsigned)((warp_n * 16 + (lane & 7) + ((lane >> 4) & 1) * 8) * PITCH
                                + ((lane >> 3) & 1) * 4) * 4;

    float c1[4][2][4], c2[4][2][4];
#pragma unroll
    for (int mt = 0; mt < 4; mt++)
#pragma unroll
        for (int nt = 0; nt < 2; nt++)
#pragma unroll
            for (int j = 0; j < 4; j++) { c1[mt][nt][j] = 0.f; c2[mt][nt][j] = 0.f; }

    int st_c = 0, st_p = 2;
    for (int it = 0; it < G1_NIT; it++) {
        asm volatile("cp.async.wait_group 1;" ::: "memory");
        __syncthreads();
        unsigned Ab  = sbase + st_c * (G1_STG * 4);
        unsigned B1b = Ab + G1_ASZ * 4;
        unsigned B2b = B1b + G1_BSZ * 4;
#pragma unroll
        for (int kk = 0; kk < 32; kk += 8) {
            unsigned a[4][4], b1[4], b2[4];
#pragma unroll
            for (int mt = 0; mt < 4; mt++)
                ldsm4(a[mt], Ab + a_off + (unsigned)(mt * 16 * PITCH + kk) * 4);
            ldsm4(b1, B1b + b_off + (unsigned)kk * 4);
            ldsm4(b2, B2b + b_off + (unsigned)kk * 4);
#pragma unroll
            for (int g = 0; g < 2; g++)
#pragma unroll
                for (int mt = 0; mt < 4; mt++) {
                    mma_tf32(c1[mt][g], a[mt], b1[2 * g], b1[2 * g + 1]);
                    mma_tf32(c2[mt][g], a[mt], b2[2 * g], b2[2 * g + 1]);
                }
        }
        if (it + 2 < G1_NIT) {
            unsigned sb = sbase + st_p * (G1_STG * 4);
            int k0 = (it + 2) * 32;
#pragma unroll
            for (int j = 0; j < 4; j++) cpa16(sb + adst[j], asrc[j] + k0);
#pragma unroll
            for (int j = 0; j < 4; j++) cpa16(sb + bdst[j], bsrc[j] + k0);
        }
        asm volatile("cp.async.commit_group;" ::: "memory");
        st_c = (st_c == 2) ? 0 : st_c + 1;
        st_p = (st_p == 2) ? 0 : st_p + 1;
    }

    // epilogue: exact gelu(inp) * gate, stored tf32-rounded
#pragma unroll
    for (int mt = 0; mt < 4; mt++) {
#pragma unroll
        for (int half = 0; half < 2; half++) {
            int r = r0 + warp_m * 64 + mt * 16 + gid + half * 8;
            float* dst = g_hglu + ((size_t)(e * CAP + r)) * IDIM;
#pragma unroll
            for (int nt = 0; nt < 2; nt++) {
                float i0 = c1[mt][nt][2 * half + 0];
                float i1 = c1[mt][nt][2 * half + 1];
                float g0 = 0.5f * i0 * (1.0f + erff(i0 * 0.70710678118654752f));
                float g1 = 0.5f * i1 * (1.0f + erff(i1 * 0.70710678118654752f));
                float2 v;
                v.x = __uint_as_float(f2tf32(g0 * c2[mt][nt][2 * half + 0]));
                v.y = __uint_as_float(f2tf32(g1 * c2[mt][nt][2 * half + 1]));
                int col = n0 + warp_n * 16 + nt * 8 + 2 * tid4;
                *(float2*)(dst + col) = v;
            }
        }
    }
}

// ---------------------------------------------------------------------------
// GEMM2: block 128m x 128n, 256 thr, 8 warps (2x4), warp 64m x 32n.
// 3-stage cp.async, 2 CTAs/SM. ldmatrix fragments, pitch 36.
// ---------------------------------------------------------------------------
#define G2_ASZ (128 * PITCH)             // 4608 u32
#define G2_BSZ (128 * PITCH)             // 4608 u32
#define G2_STG (G2_ASZ + G2_BSZ)         // 9216 u32
#define G2_NIT (IDIM / 32)               // 64
#define SMEM2_BYTES (3 * G2_STG * 4)     // 110592

__global__ __launch_bounds__(256, 2) void gemm2_kernel(const unsigned* __restrict__ w2t,
                                                       float* __restrict__ out) {
    extern __shared__ unsigned sm2[];

    int e   = blockIdx.z;
    int cnt = g_count[e];
    int r0  = blockIdx.y * 128;
    if (r0 >= cnt) return;
    int n0  = blockIdx.x * 128;
    int tid = threadIdx.x;
    int lane = tid & 31, warp = tid >> 5;
    int gid = lane >> 2, tid4 = lane & 3;
    int warp_m = warp >> 2;    // 0..1
    int warp_n = warp & 3;     // 0..3

    unsigned sbase = smem_u32(sm2);
    const unsigned* hbase = (const unsigned*)g_hglu + (size_t)e * CAP * IDIM;
    const unsigned* w2e   = w2t + (size_t)e * DIM * IDIM;

    const unsigned* asrc[4]; unsigned adst[4];
#pragma unroll
    for (int j = 0; j < 4; j++) {
        int c = tid + 256 * j;
        int row = c >> 3, ch = c & 7;
        asrc[j] = hbase + (size_t)(r0 + row) * IDIM + ch * 4;
        adst[j] = (unsigned)(row * PITCH + ch * 4) * 4;
    }
    const unsigned* bsrc[4]; unsigned bdst[4];
#pragma unroll
    for (int j = 0; j < 4; j++) {
        int c = tid + 256 * j;
        int r = c >> 3, ch = c & 7;                 // r: 0..127
        bsrc[j] = w2e + (size_t)(n0 + r) * IDIM + ch * 4;
        bdst[j] = (unsigned)(G2_ASZ + r * PITCH + ch * 4) * 4;
    }

#pragma unroll
    for (int s = 0; s < 2; s++) {
        unsigned sb = sbase + s * (G2_STG * 4);
        int k0 = s * 32;
#pragma unroll
        for (int j = 0; j < 4; j++) cpa16(sb + adst[j], asrc[j] + k0);
#pragma unroll
        for (int j = 0; j < 4; j++) cpa16(sb + bdst[j], bsrc[j] + k0);
        asm volatile("cp.async.commit_group;" ::: "memory");
    }

    unsigned a_off = (unsigned)((warp_m * 64 + (lane & 15)) * PITCH + (lane >> 4) * 4) * 4;
    unsigned b_off = (unsigned)((warp_n * 32 + (lane & 7) + ((lane >> 4) & 1) * 8) * PITCH
                                + ((lane >> 3) & 1) * 4) * 4;

    float c[4][4][4];
#pragma unroll
    for (int mt = 0; mt < 4; mt++)
#pragma unroll
        for (int nt = 0; nt < 4; nt++)
#pragma unroll
            for (int j = 0; j < 4; j++) c[mt][nt][j] = 0.f;

    int st_c = 0, st_p = 2;
    for (int it = 0; it < G2_NIT; it++) {
        asm volatile("cp.async.wait_group 1;" ::: "memory");
        __syncthreads();
        unsigned Ab = sbase + st_c * (G2_STG * 4);
        unsigned Bb = Ab + G2_ASZ * 4;
#pragma unroll
        for (int kk = 0; kk < 32; kk += 8) {
            unsigned a[4][4], bf[2][4];
#pragma unroll
            for (int mt = 0; mt < 4; mt++)
                ldsm4(a[mt], Ab + a_off + (unsigned)(mt * 16 * PITCH + kk) * 4);
#pragma unroll
            for (int p = 0; p < 2; p++)
                ldsm4(bf[p], Bb + b_off + (unsigned)(p * 16 * PITCH + kk) * 4);
#pragma unroll
            for (int nt = 0; nt < 4; nt++) {
                unsigned b0 = bf[nt >> 1][(nt & 1) * 2];
                unsigned b1 = bf[nt >> 1][(nt & 1) * 2 + 1];
#pragma unroll
                for (int mt = 0; mt < 4; mt++)
                    mma_tf32(c[mt][nt], a[mt], b0, b1);
            }
        }
        if (it + 2 < G2_NIT) {
            unsigned sb = sbase + st_p * (G2_STG * 4);
            int k0 = (it + 2) * 32;
#pragma unroll
            for (int j = 0; j < 4; j++) cpa16(sb + adst[j], asrc[j] + k0);
#pragma unroll
            for (int j = 0; j < 4; j++) cpa16(sb + bdst[j], bsrc[j] + k0);
        }
        asm volatile("cp.async.commit_group;" ::: "memory");
        st_c = (st_c == 2) ? 0 : st_c + 1;
        st_p = (st_p == 2) ? 0 : st_p + 1;
    }

    // gate-weighted scatter
#pragma unroll
    for (int mt = 0; mt < 4; mt++) {
#pragma unroll
        for (int half = 0; half < 2; half++) {
            int r = r0 + warp_m * 64 + mt * 16 + gid + half * 8;
            if (r < cnt) {
                int tok   = g_row2tok[e * CAP + r];
                float gte = g_rowgate[e * CAP + r];
                float* op = out + (size_t)tok * DIM + n0 + warp_n * 32 + 2 * tid4;
#pragma unroll
                for (int nt = 0; nt < 4; nt++) {
                    float v0 = gte * c[mt][nt][2 * half + 0];
                    float v1 = gte * c[mt][nt][2 * half + 1];
                    asm volatile("red.global.add.v2.f32 [%0], {%1, %2};"
                                 :: "l"(op + nt * 8), "f"(v0), "f"(v1) : "memory");
                }
            }
        }
    }
}

// ---------------------------------------------------------------------------
extern "C" void kernel_launch(void* const* d_in, const int* in_sizes, int n_in,
                              void* d_out, int out_size) {
    const float* x  = (const float*)d_in[0];
    const float* Wg = (const float*)d_in[1];
    const float* W1 = (const float*)d_in[2];
    const float* W2 = (const float*)d_in[3];
    float* out = (float*)d_out;

    cudaFuncSetAttribute(gemm1_kernel, cudaFuncAttributeMaxDynamicSharedMemorySize, SMEM1_BYTES);
    cudaFuncSetAttribute(gemm2_kernel, cudaFuncAttributeMaxDynamicSharedMemorySize, SMEM2_BYTES);

    unsigned *w1t, *w2t, *xc;
    cudaGetSymbolAddress((void**)&xc,  g_xc);
    cudaGetSymbolAddress((void**)&w1t, g_w1t);
    cudaGetSymbolAddress((void**)&w2t, g_w2t);

    cudaMemsetAsync(out, 0, (size_t)NTOK * DIM * sizeof(float));

    // pre: router(+x->tf32) and W1 transpose, concurrent in one launch
    pre_kernel<<<PRE_ROUTER_BLOCKS + W1T_TILES, 256>>>(x, Wg, W1);
    scan_kernel<<<1, 256>>>();

    // gemm1 (+ W2 transpose in extra z-slices, overlapped)
    dim3 g1(G1_XB, G1_YB, NEXP + W2T_ZSLICES);    // (32, 10, 60)
    gemm1_kernel<<<g1, 256, SMEM1_BYTES>>>(xc, w1t, W2);

    dim3 g2(DIM / 128, CAP / 128, NEXP);          // (8, 10, 8)
    gemm2_kernel<<<g2, 256, SMEM2_BYTES>>>(w2t, out);
}

// round 17
// speedup vs baseline: 5.2414x; 1.3922x over previous
#include <cuda_runtime.h>
#include <cuda_fp16.h>
#include <math.h>

// Problem constants
#define NTOK 4096
#define DIM  1024
#define NEXP 8
#define IDIM 2048
#define CAP  1280
#define NSLOT (NTOK*2)

// Scratch (static; no cudaMalloc allowed)
__device__ __half g_hglu[(size_t)NEXP * CAP * IDIM];        // 42 MB fp16 GLU acts
__device__ __half g_xh [(size_t)NTOK * DIM];                // x fp16, [tok][k]
__device__ __half g_w1h[(size_t)NEXP * 2 * IDIM * DIM];     // W1^T fp16, [e][n][k]
__device__ __half g_w2h[(size_t)NEXP * DIM * IDIM];         // W2^T fp16, [e][n][k]
__device__ int   g_row2tok[NEXP * CAP];
__device__ float g_rowgate[NEXP * CAP];
__device__ int   g_count[NEXP];
__device__ int   g_slot_e[NSLOT];
__device__ float g_slot_g[NSLOT];

__device__ __forceinline__ void mma_f16(float* c, const unsigned* a, unsigned b0, unsigned b1) {
    asm volatile(
        "mma.sync.aligned.m16n8k16.row.col.f32.f16.f16.f32 "
        "{%0,%1,%2,%3}, {%4,%5,%6,%7}, {%8,%9}, {%0,%1,%2,%3};\n"
        : "+f"(c[0]), "+f"(c[1]), "+f"(c[2]), "+f"(c[3])
        : "r"(a[0]), "r"(a[1]), "r"(a[2]), "r"(a[3]), "r"(b0), "r"(b1));
}
__device__ __forceinline__ void cpa16(unsigned smem_addr, const void* gptr) {
    asm volatile("cp.async.cg.shared.global [%0], [%1], 16;"
                 :: "r"(smem_addr), "l"(gptr) : "memory");
}
__device__ __forceinline__ void ldsm4(unsigned* r, unsigned addr) {
    asm volatile("ldmatrix.sync.aligned.m8n8.x4.shared.b16 {%0,%1,%2,%3}, [%4];"
                 : "=r"(r[0]), "=r"(r[1]), "=r"(r[2]), "=r"(r[3]) : "r"(addr));
}
__device__ __forceinline__ unsigned smem_u32(const void* p) {
    unsigned a;
    asm("{ .reg .u64 t; cvta.to.shared.u64 t, %1; cvt.u32.u64 %0, t; }" : "=r"(a) : "l"(p));
    return a;
}

// ---------------------------------------------------------------------------
// Pre-kernel: blocks [0,512) = router (also emits x as fp16 into g_xh).
//             blocks [512, 512+32768) = W1 transpose+convert -> g_w1h.
// ---------------------------------------------------------------------------
#define PRE_ROUTER_BLOCKS 512
#define W1T_TILES (NEXP * (DIM / 32) * (2 * IDIM / 32))   // 32768

__global__ __launch_bounds__(256) void pre_kernel(const float* __restrict__ x,
                                                  const float* __restrict__ Wg,
                                                  const float* __restrict__ W1) {
    __shared__ float t[32][33];
    int b = blockIdx.x;
    int tid = threadIdx.x;

    if (b < PRE_ROUTER_BLOCKS) {
        // ------- router -------
        int warp = b * 8 + (tid >> 5);
        int lane = tid & 31;
        const float* xr = x + (size_t)warp * DIM;
        __half* xho = g_xh + (size_t)warp * DIM;
        float acc[NEXP];
#pragma unroll
        for (int e = 0; e < NEXP; e++) acc[e] = 0.f;
        for (int i = lane; i < DIM; i += 32) {
            float xv = __ldg(xr + i);
            xho[i] = __float2half_rn(xv);
#pragma unroll
            for (int e = 0; e < NEXP; e++) acc[e] += xv * __ldg(Wg + e * DIM + i);
        }
#pragma unroll
        for (int e = 0; e < NEXP; e++) {
#pragma unroll
            for (int off = 16; off > 0; off >>= 1)
                acc[e] += __shfl_xor_sync(0xffffffffu, acc[e], off);
        }
        if (lane == 0) {
            int i0 = 0; float v0 = acc[0];
#pragma unroll
            for (int e = 1; e < NEXP; e++) if (acc[e] > v0) { v0 = acc[e]; i0 = e; }
            int i1 = -1; float v1 = -1e30f;
#pragma unroll
            for (int e = 0; e < NEXP; e++)
                if (e != i0 && acc[e] > v1) { v1 = acc[e]; i1 = e; }
            float e0 = expf(v0 - v0), e1 = expf(v1 - v0);
            float inv = 1.0f / (e0 + e1);
            g_slot_e[2 * warp + 0] = i0; g_slot_g[2 * warp + 0] = e0 * inv;
            g_slot_e[2 * warp + 1] = i1; g_slot_g[2 * warp + 1] = e1 * inv;
        }
    } else {
        // ------- W1 transpose: src[e][DIM][2*IDIM] -> dst[e][2*IDIM][DIM] fp16
        int bp = b - PRE_ROUTER_BLOCKS;
        int e   = bp >> 12;
        int rem = bp & 4095;
        int rt  = rem >> 7;
        int ct  = rem & 127;
        int r0 = rt * 32, c0 = ct * 32;
        const int R = DIM, C = 2 * IDIM;
        const float* s = W1 + (size_t)e * R * C;
        __half* d = g_w1h + (size_t)e * R * C;
        int tx = tid & 31, ty = tid >> 5;
#pragma unroll
        for (int j = 0; j < 32; j += 8)
            t[ty + j][tx] = s[(size_t)(r0 + ty + j) * C + c0 + tx];
        __syncthreads();
#pragma unroll
        for (int j = 0; j < 32; j += 8)
            d[(size_t)(c0 + ty + j) * R + r0 + tx] = __float2half_rn(t[tx][ty + j]);
    }
}

// ---------------------------------------------------------------------------
// Capacity scan
// ---------------------------------------------------------------------------
__global__ void scan_kernel() {
    __shared__ int smc[256][NEXP];
    int tid = threadIdx.x;
    for (int i = tid; i < NEXP * CAP; i += 256) {
        g_row2tok[i] = 0;
        g_rowgate[i] = 0.f;
    }
    const int PER = NSLOT / 256;
    int s0 = tid * PER;
    int le[PER];
    int c[NEXP];
#pragma unroll
    for (int e = 0; e < NEXP; e++) c[e] = 0;
#pragma unroll
    for (int j = 0; j < PER; j++) {
        int e = g_slot_e[s0 + j];
        le[j] = e;
        c[e]++;
    }
#pragma unroll
    for (int e = 0; e < NEXP; e++) smc[tid][e] = c[e];
    __syncthreads();
    if (tid < NEXP) {
        int run = 0;
        for (int t = 0; t < 256; t++) {
            int v = smc[t][tid];
            smc[t][tid] = run;
            run += v;
        }
        g_count[tid] = run < CAP ? run : CAP;
    }
    __syncthreads();
    int off[NEXP];
#pragma unroll
    for (int e = 0; e < NEXP; e++) off[e] = smc[tid][e];
#pragma unroll
    for (int j = 0; j < PER; j++) {
        int e = le[j];
        int p = off[e]++;
        if (p < CAP) {
            int slot = s0 + j;
            g_row2tok[e * CAP + p] = slot >> 1;
            g_rowgate[e * CAP + p] = g_slot_g[slot];
        }
    }
}

// ---------------------------------------------------------------------------
// GEMM1 (fp16 mma m16n8k16): block 128m x 64 pair-cols, 256 thr, 8 warps.
// Warp tile 64m x 16pair. Stage k=32 halfs, pitch 40 halfs, 4-stage cp.async,
// 2 CTAs/SM. Extra blockIdx.z slices (z>=8): W2 transpose -> g_w2h.
// ---------------------------------------------------------------------------
#define PH 40                            // pitch in halfs (80 B rows)
#define G1_A_B (128 * PH * 2)            // 10240 bytes (A region)
#define G1_B_B (128 * PH * 2)            // 10240 bytes (B region: 2 mats x 64 rows)
#define G1_STG_B (G1_A_B + G1_B_B)       // 20480 bytes
#define G1_NIT (DIM / 32)                // 32
#define SMEM1_BYTES (4 * G1_STG_B + 512) // 82432

#define W2T_TILES (NEXP * (IDIM / 32) * (DIM / 32))   // 16384
#define G1_XB 32
#define G1_YB (CAP / 128)                              // 10
#define W2T_ZSLICES ((W2T_TILES + G1_XB * G1_YB - 1) / (G1_XB * G1_YB))  // 52

__global__ __launch_bounds__(256, 2) void gemm1_kernel(const __half* __restrict__ xh,
                                                       const __half* __restrict__ w1h,
                                                       const float* __restrict__ W2) {
    extern __shared__ unsigned sm1[];

    if (blockIdx.z >= NEXP) {
        // ------- W2 transpose: src[e][IDIM][DIM] -> dst[e][DIM][IDIM] fp16
        int tile = (blockIdx.z - NEXP) * (G1_XB * G1_YB) + blockIdx.y * G1_XB + blockIdx.x;
        if (tile >= W2T_TILES) return;
        float* t = (float*)sm1;                       // [32][33]
        int e   = tile >> 11;
        int rem = tile & 2047;
        int rt  = rem >> 5;
        int ct  = rem & 31;
        int r0 = rt * 32, c0 = ct * 32;
        const int R = IDIM, C = DIM;
        const float* s = W2 + (size_t)e * R * C;
        __half* d = g_w2h + (size_t)e * R * C;
        int tid = threadIdx.x;
        int tx = tid & 31, ty = tid >> 5;
#pragma unroll
        for (int j = 0; j < 32; j += 8)
            t[(ty + j) * 33 + tx] = s[(size_t)(r0 + ty + j) * C + c0 + tx];
        __syncthreads();
#pragma unroll
        for (int j = 0; j < 32; j += 8)
            d[(size_t)(c0 + ty + j) * R + r0 + tx] = __float2half_rn(t[tx * 33 + ty + j]);
        return;
    }

    int* stok = (int*)((char*)sm1 + 4 * G1_STG_B);

    int e   = blockIdx.z;
    int cnt = g_count[e];
    int r0  = blockIdx.y * 128;
    if (r0 >= cnt) return;
    int n0  = blockIdx.x * 64;
    int tid = threadIdx.x;
    int lane = tid & 31, warp = tid >> 5;
    int gid = lane >> 2, tid4 = lane & 3;
    int warp_m = warp >> 2;    // 0..1
    int warp_n = warp & 3;     // 0..3

    if (tid < 128) stok[tid] = g_row2tok[e * CAP + r0 + tid];
    __syncthreads();

    unsigned sbase = smem_u32(sm1);

    // A loader: 512 chunks (128 rows x 4 chunks of 8 halfs), 2/thread
    const __half* asrc[2]; unsigned adst[2];
#pragma unroll
    for (int j = 0; j < 2; j++) {
        int c = tid + 256 * j;
        int row = c >> 2, ch = c & 3;
        asrc[j] = xh + (size_t)stok[row] * DIM + ch * 8;
        adst[j] = (unsigned)(row * PH + ch * 8) * 2;
    }
    // B loader: 512 chunks (128 rows: mat = r>>6), 2/thread
    const __half* bsrc[2]; unsigned bdst[2];
#pragma unroll
    for (int j = 0; j < 2; j++) {
        int c = tid + 256 * j;
        int r = c >> 2, ch = c & 3;
        int n = (r >> 6) * IDIM + n0 + (r & 63);
        bsrc[j] = w1h + ((size_t)e * 2 * IDIM + n) * DIM + ch * 8;
        bdst[j] = (unsigned)G1_A_B + (unsigned)(r * PH + ch * 8) * 2;
    }

#pragma unroll
    for (int s = 0; s < 3; s++) {
        unsigned sb = sbase + s * G1_STG_B;
        int k0 = s * 32;
#pragma unroll
        for (int j = 0; j < 2; j++) cpa16(sb + adst[j], asrc[j] + k0);
#pragma unroll
        for (int j = 0; j < 2; j++) cpa16(sb + bdst[j], bsrc[j] + k0);
        asm volatile("cp.async.commit_group;" ::: "memory");
    }

    unsigned a_off = (unsigned)((lane & 15) * PH + (lane >> 4) * 8) * 2;
    unsigned b_off = (unsigned)((warp_n * 16 + (lane & 15)) * PH + (lane >> 4) * 8) * 2;

    float c1[4][2][4], c2[4][2][4];
#pragma unroll
    for (int mt = 0; mt < 4; mt++)
#pragma unroll
        for (int nt = 0; nt < 2; nt++)
#pragma unroll
            for (int j = 0; j < 4; j++) { c1[mt][nt][j] = 0.f; c2[mt][nt][j] = 0.f; }

    for (int it = 0; it < G1_NIT; it++) {
        asm volatile("cp.async.wait_group 2;" ::: "memory");
        __syncthreads();
        unsigned Ab  = sbase + (it & 3) * G1_STG_B + (unsigned)(warp_m * 64 * PH) * 2;
        unsigned B1b = sbase + (it & 3) * G1_STG_B + G1_A_B;
        unsigned B2b = B1b + (unsigned)(64 * PH) * 2;
#pragma unroll
        for (int kk = 0; kk < 32; kk += 16) {
            unsigned a[4][4], b1f[4], b2f[4];
#pragma unroll
            for (int mt = 0; mt < 4; mt++)
                ldsm4(a[mt], Ab + a_off + (unsigned)(mt * 16 * PH + kk) * 2);
            ldsm4(b1f, B1b + b_off + (unsigned)kk * 2);
            ldsm4(b2f, B2b + b_off + (unsigned)kk * 2);
#pragma unroll
            for (int g = 0; g < 2; g++)
#pragma unroll
                for (int mt = 0; mt < 4; mt++) {
                    mma_f16(c1[mt][g], a[mt], b1f[g], b1f[g + 2]);
                    mma_f16(c2[mt][g], a[mt], b2f[g], b2f[g + 2]);
                }
        }
        if (it + 3 < G1_NIT) {
            unsigned sb = sbase + ((it + 3) & 3) * G1_STG_B;
            int k0 = (it + 3) * 32;
#pragma unroll
            for (int j = 0; j < 2; j++) cpa16(sb + adst[j], asrc[j] + k0);
#pragma unroll
            for (int j = 0; j < 2; j++) cpa16(sb + bdst[j], bsrc[j] + k0);
        }
        asm volatile("cp.async.commit_group;" ::: "memory");
    }

    // epilogue: exact gelu(inp) * gate, stored fp16
#pragma unroll
    for (int mt = 0; mt < 4; mt++) {
#pragma unroll
        for (int half_ = 0; half_ < 2; half_++) {
            int r = r0 + warp_m * 64 + mt * 16 + gid + half_ * 8;
            __half* dst = g_hglu + ((size_t)(e * CAP + r)) * IDIM;
#pragma unroll
            for (int nt = 0; nt < 2; nt++) {
                float i0 = c1[mt][nt][2 * half_ + 0];
                float i1 = c1[mt][nt][2 * half_ + 1];
                float g0 = 0.5f * i0 * (1.0f + erff(i0 * 0.70710678118654752f));
                float g1 = 0.5f * i1 * (1.0f + erff(i1 * 0.70710678118654752f));
                __half2 v = __floats2half2_rn(g0 * c2[mt][nt][2 * half_ + 0],
                                              g1 * c2[mt][nt][2 * half_ + 1]);
                int col = n0 + warp_n * 16 + nt * 8 + 2 * tid4;
                *(__half2*)(dst + col) = v;
            }
        }
    }
}

// ---------------------------------------------------------------------------
// GEMM2 (fp16 mma): block 128m x 128n, 256 thr, warp 64m x 32n.
// Stage k=32 halfs, pitch 40, 4-stage cp.async, 2 CTAs/SM.
// ---------------------------------------------------------------------------
#define G2_A_B (128 * PH * 2)            // 10240
#define G2_B_B (128 * PH * 2)            // 10240
#define G2_STG_B (G2_A_B + G2_B_B)       // 20480
#define G2_NIT (IDIM / 32)               // 64
#define SMEM2_BYTES (4 * G2_STG_B)       // 81920

__global__ __launch_bounds__(256, 2) void gemm2_kernel(const __half* __restrict__ w2h,
                                                       float* __restrict__ out) {
    extern __shared__ unsigned sm2[];

    int e   = blockIdx.z;
    int cnt = g_count[e];
    int r0  = blockIdx.y * 128;
    if (r0 >= cnt) return;
    int n0  = blockIdx.x * 128;
    int tid = threadIdx.x;
    int lane = tid & 31, warp = tid >> 5;
    int gid = lane >> 2, tid4 = lane & 3;
    int warp_m = warp >> 2;    // 0..1
    int warp_n = warp & 3;     // 0..3

    unsigned sbase = smem_u32(sm2);
    const __half* hbase = g_hglu + (size_t)e * CAP * IDIM;
    const __half* w2e   = w2h + (size_t)e * DIM * IDIM;

    const __half* asrc[2]; unsigned adst[2];
#pragma unroll
    for (int j = 0; j < 2; j++) {
        int c = tid + 256 * j;
        int row = c >> 2, ch = c & 3;
        asrc[j] = hbase + (size_t)(r0 + row) * IDIM + ch * 8;
        adst[j] = (unsigned)(row * PH + ch * 8) * 2;
    }
    const __half* bsrc[2]; unsigned bdst[2];
#pragma unroll
    for (int j = 0; j < 2; j++) {
        int c = tid + 256 * j;
        int r = c >> 2, ch = c & 3;
        bsrc[j] = w2e + (size_t)(n0 + r) * IDIM + ch * 8;
        bdst[j] = (unsigned)G2_A_B + (unsigned)(r * PH + ch * 8) * 2;
    }

#pragma unroll
    for (int s = 0; s < 3; s++) {
        unsigned sb = sbase + s * G2_STG_B;
        int k0 = s * 32;
#pragma unroll
        for (int j = 0; j < 2; j++) cpa16(sb + adst[j], asrc[j] + k0);
#pragma unroll
        for (int j = 0; j < 2; j++) cpa16(sb + bdst[j], bsrc[j] + k0);
        asm volatile("cp.async.commit_group;" ::: "memory");
    }

    unsigned a_off = (unsigned)((lane & 15) * PH + (lane >> 4) * 8) * 2;
    unsigned b_off = (unsigned)((warp_n * 32 + (lane & 15)) * PH + (lane >> 4) * 8) * 2;

    float c[4][4][4];
#pragma unroll
    for (int mt = 0; mt < 4; mt++)
#pragma unroll
        for (int nt = 0; nt < 4; nt++)
#pragma unroll
            for (int j = 0; j < 4; j++) c[mt][nt][j] = 0.f;

    for (int it = 0; it < G2_NIT; it++) {
        asm volatile("cp.async.wait_group 2;" ::: "memory");
        __syncthreads();
        unsigned Ab = sbase + (it & 3) * G2_STG_B + (unsigned)(warp_m * 64 * PH) * 2;
        unsigned Bb = sbase + (it & 3) * G2_STG_B + G2_A_B;
#pragma unroll
        for (int kk = 0; kk < 32; kk += 16) {
            unsigned a[4][4], bfp[2][4];
#pragma unroll
            for (int mt = 0; mt < 4; mt++)
                ldsm4(a[mt], Ab + a_off + (unsigned)(mt * 16 * PH + kk) * 2);
#pragma unroll
            for (int p = 0; p < 2; p++)
                ldsm4(bfp[p], Bb + b_off + (unsigned)(p * 16 * PH + kk) * 2);
#pragma unroll
            for (int nt = 0; nt < 4; nt++) {
                unsigned b0 = bfp[nt >> 1][(nt & 1)];
                unsigned b1 = bfp[nt >> 1][(nt & 1) + 2];
#pragma unroll
                for (int mt = 0; mt < 4; mt++)
                    mma_f16(c[mt][nt], a[mt], b0, b1);
            }
        }
        if (it + 3 < G2_NIT) {
            unsigned sb = sbase + ((it + 3) & 3) * G2_STG_B;
            int k0 = (it + 3) * 32;
#pragma unroll
            for (int j = 0; j < 2; j++) cpa16(sb + adst[j], asrc[j] + k0);
#pragma unroll
            for (int j = 0; j < 2; j++) cpa16(sb + bdst[j], bsrc[j] + k0);
        }
        asm volatile("cp.async.commit_group;" ::: "memory");
    }

    // gate-weighted scatter
#pragma unroll
    for (int mt = 0; mt < 4; mt++) {
#pragma unroll
        for (int half_ = 0; half_ < 2; half_++) {
            int r = r0 + warp_m * 64 + mt * 16 + gid + half_ * 8;
            if (r < cnt) {
                int tok   = g_row2tok[e * CAP + r];
                float gte = g_rowgate[e * CAP + r];
                float* op = out + (size_t)tok * DIM + n0 + warp_n * 32 + 2 * tid4;
#pragma unroll
                for (int nt = 0; nt < 4; nt++) {
                    float v0 = gte * c[mt][nt][2 * half_ + 0];
                    float v1 = gte * c[mt][nt][2 * half_ + 1];
                    asm volatile("red.global.add.v2.f32 [%0], {%1, %2};"
                                 :: "l"(op + nt * 8), "f"(v0), "f"(v1) : "memory");
                }
            }
        }
    }
}

// ---------------------------------------------------------------------------
extern "C" void kernel_launch(void* const* d_in, const int* in_sizes, int n_in,
                              void* d_out, int out_size) {
    const float* x  = (const float*)d_in[0];
    const float* Wg = (const float*)d_in[1];
    const float* W1 = (const float*)d_in[2];
    const float* W2 = (const float*)d_in[3];
    float* out = (float*)d_out;

    cudaFuncSetAttribute(gemm1_kernel, cudaFuncAttributeMaxDynamicSharedMemorySize, SMEM1_BYTES);
    cudaFuncSetAttribute(gemm2_kernel, cudaFuncAttributeMaxDynamicSharedMemorySize, SMEM2_BYTES);

    __half *xh, *w1h, *w2h;
    cudaGetSymbolAddress((void**)&xh,  g_xh);
    cudaGetSymbolAddress((void**)&w1h, g_w1h);
    cudaGetSymbolAddress((void**)&w2h, g_w2h);

    cudaMemsetAsync(out, 0, (size_t)NTOK * DIM * sizeof(float));

    // pre: router(+x->fp16) and W1 transpose, concurrent in one launch
    pre_kernel<<<PRE_ROUTER_BLOCKS + W1T_TILES, 256>>>(x, Wg, W1);
    scan_kernel<<<1, 256>>>();

    // gemm1 (+ W2 transpose in extra z-slices, overlapped)
    dim3 g1(G1_XB, G1_YB, NEXP + W2T_ZSLICES);    // (32, 10, 60)
    gemm1_kernel<<<g1, 256, SMEM1_BYTES>>>(xh, w1h, W2);

    dim3 g2(DIM / 128, CAP / 128, NEXP);          // (8, 10, 8)
    gemm2_kernel<<<g2, 256, SMEM2_BYTES>>>(w2h, out);
}